// round 1
// baseline (speedup 1.0000x reference)
#include <cuda_runtime.h>
#include <cstdint>

// ---------------------------------------------------------------------------
// Problem constants (Qwen2.5-style attention block)
// ---------------------------------------------------------------------------
constexpr int HID_C = 2048;   // hidden size
constexpr int H_C   = 16;     // q heads
constexpr int KV_C  = 2;      // kv heads
constexpr int D_C   = 128;    // head dim
constexpr int MAXM  = 4096;   // max B*L rows

// ---------------------------------------------------------------------------
// Scratch (static __device__ arrays; no allocation anywhere)
// ---------------------------------------------------------------------------
__device__ float g_q[MAXM * HID_C];          // [M][H*D]   (row-major)
__device__ float g_k[MAXM * KV_C * D_C];     // [M][KV*D]
__device__ float g_v[MAXM * KV_C * D_C];     // [M][KV*D]
__device__ float g_attn[MAXM * HID_C];       // [M][H*D]

// ---------------------------------------------------------------------------
// Generic NT GEMM:  C[m,n] = sum_k A[m,k] * B[n,k] (+ bias[n])
// A: [M][K] row-major, B: [N][K] row-major, C: [M][N] row-major.
// 128x128x32 tiles, cp.async double buffering, 8x8 register micro-tiles.
// ---------------------------------------------------------------------------
constexpr int BM = 128, BN = 128, BK = 32;
constexpr int LDT = BK + 4;                           // padded smem row (36)
constexpr int GEMM_SMEM = 2 * 2 * BM * LDT * 4;       // 73728 bytes

__device__ __forceinline__ uint32_t smem_u32(const void* p) {
  return (uint32_t)__cvta_generic_to_shared(p);
}
__device__ __forceinline__ void cp_async16(uint32_t dst, const void* src) {
  asm volatile("cp.async.cg.shared.global [%0], [%1], 16;" :: "r"(dst), "l"(src));
}
__device__ __forceinline__ void cp_commit() {
  asm volatile("cp.async.commit_group;");
}
__device__ __forceinline__ void cp_wait1() {
  asm volatile("cp.async.wait_group 1;");
}
__device__ __forceinline__ void cp_wait0() {
  asm volatile("cp.async.wait_group 0;");
}

template <bool HAS_BIAS>
__global__ void __launch_bounds__(256, 2)
gemm_nt(const float* __restrict__ A, const float* __restrict__ B,
        const float* __restrict__ bias, float* __restrict__ C,
        int M, int N, int K) {
  extern __shared__ float sm[];
  float* As = sm;                   // [2][BM][LDT]
  float* Bs = sm + 2 * BM * LDT;    // [2][BN][LDT]

  const int tid = threadIdx.x;
  const int m0 = blockIdx.y * BM;
  const int n0 = blockIdx.x * BN;
  const int ty = tid >> 4;          // 0..15 -> rows ty+16i (strided: LDS broadcast-safe)
  const int tx = tid & 15;          // 0..15 -> cols tx+16j
  const int lrow = tid >> 3;        // 0..31
  const int lcol = (tid & 7) << 2;  // 0,4,...,28

  const float* Ag = A + (size_t)(m0 + lrow) * K + lcol;
  const float* Bg = B + (size_t)(n0 + lrow) * K + lcol;
  const uint32_t sA = smem_u32(As) + ((lrow * LDT + lcol) << 2);
  const uint32_t sB = smem_u32(Bs) + ((lrow * LDT + lcol) << 2);
  constexpr uint32_t BUFB = BM * LDT * 4;   // bytes between double buffers
  constexpr uint32_t R32  = 32 * LDT * 4;   // bytes per 32 smem rows

  const int KT = K / BK;

  // prologue: tile 0 -> buffer 0
#pragma unroll
  for (int i = 0; i < 4; ++i) {
    cp_async16(sA + i * R32, Ag + (size_t)i * 32 * K);
    cp_async16(sB + i * R32, Bg + (size_t)i * 32 * K);
  }
  cp_commit();

  float acc[8][8];
#pragma unroll
  for (int i = 0; i < 8; ++i)
#pragma unroll
    for (int j = 0; j < 8; ++j) acc[i][j] = 0.f;

  for (int kt = 0; kt < KT; ++kt) {
    const int cur = kt & 1;
    if (kt + 1 < KT) {
      const uint32_t off = (uint32_t)(cur ^ 1) * BUFB;
      const size_t gofs = (size_t)(kt + 1) * BK;
#pragma unroll
      for (int i = 0; i < 4; ++i) {
        cp_async16(sA + off + i * R32, Ag + (size_t)i * 32 * K + gofs);
        cp_async16(sB + off + i * R32, Bg + (size_t)i * 32 * K + gofs);
      }
      cp_commit();
      cp_wait1();
    } else {
      cp_wait0();
    }
    __syncthreads();

    const float* Ac = As + cur * BM * LDT;
    const float* Bc = Bs + cur * BM * LDT;
#pragma unroll 4
    for (int kk = 0; kk < BK; ++kk) {
      float a[8], b[8];
#pragma unroll
      for (int i = 0; i < 8; ++i) a[i] = Ac[(ty + 16 * i) * LDT + kk];
#pragma unroll
      for (int j = 0; j < 8; ++j) b[j] = Bc[(tx + 16 * j) * LDT + kk];
#pragma unroll
      for (int i = 0; i < 8; ++i)
#pragma unroll
        for (int j = 0; j < 8; ++j) acc[i][j] = fmaf(a[i], b[j], acc[i][j]);
    }
    __syncthreads();
  }

  float bfr[8];
#pragma unroll
  for (int j = 0; j < 8; ++j) bfr[j] = HAS_BIAS ? bias[n0 + tx + 16 * j] : 0.f;
#pragma unroll
  for (int i = 0; i < 8; ++i) {
    float* Cr = C + (size_t)(m0 + ty + 16 * i) * N + n0;
#pragma unroll
    for (int j = 0; j < 8; ++j) Cr[tx + 16 * j] = acc[i][j] + bfr[j];
  }
}

// ---------------------------------------------------------------------------
// RoPE (in-place on q and k). cos/sin: [L][128] with duplicated halves.
// Each thread rotates one (d, d+64) pair.
// ---------------------------------------------------------------------------
__global__ void rope_kernel(float* __restrict__ q, float* __restrict__ k,
                            const float* __restrict__ cs, const float* __restrict__ sn,
                            int Lr, int Mr) {
  const int per = (H_C + KV_C) * 64;  // 1152 pairs per token row
  int t = blockIdx.x * blockDim.x + threadIdx.x;
  if (t >= Mr * per) return;
  int row = t / per;
  int rem = t - row * per;
  int hd = rem >> 6;    // 0..17 (0..15 = q heads, 16..17 = k heads)
  int d = rem & 63;
  int l = row % Lr;
  float c = cs[l * 128 + d];
  float s = sn[l * 128 + d];
  float* p;
  if (hd < H_C) p = q + (size_t)row * (H_C * D_C) + hd * D_C;
  else          p = k + (size_t)row * (KV_C * D_C) + (hd - H_C) * D_C;
  float x1 = p[d], x2 = p[d + 64];
  p[d]      = x1 * c - x2 * s;
  p[d + 64] = x2 * c + x1 * s;
}

// ---------------------------------------------------------------------------
// Flash attention (fp32, causal, GQA). 64x64 tiles, D=128.
// grid: (L/64, H, B), 256 threads.
// Q/K/V tiles in smem (row stride 132), P staged in smem (row stride 80).
// S phase:   thread (rg,cg) owns S[rg+16i][cg+16i'], 4x4.
// PV phase:  thread owns O rows rg+16i, cols cg*8..cg*8+7.
// ---------------------------------------------------------------------------
constexpr int FQ = 132;                                     // padded QKV row
constexpr int FP = 80;                                      // padded P row
constexpr int FLASH_SMEM = (3 * 64 * FQ + 64 * FP) * 4;     // 121856 bytes

__global__ void __launch_bounds__(256, 1)
flash_kernel(const float* __restrict__ Q, const float* __restrict__ Km,
             const float* __restrict__ Vm, float* __restrict__ O, int Lr) {
  extern __shared__ float sm[];
  float* Qs = sm;
  float* Ks = Qs + 64 * FQ;
  float* Vs = Ks + 64 * FQ;
  float* Ps = Vs + 64 * FQ;

  const int qt = blockIdx.x;
  const int h  = blockIdx.y;
  const int b  = blockIdx.z;
  const int kv = h >> 3;           // G = H/KV = 8
  const int q0 = qt * 64;
  const int tid = threadIdx.x;
  const int rg = tid >> 4;         // 0..15
  const int cg = tid & 15;         // 0..15
  const int wid = tid >> 5, lid = tid & 31;

  // Load Q tile: one warp per row, each lane a float4 (fully coalesced).
#pragma unroll
  for (int r = wid; r < 64; r += 8) {
    const float4 v = *(const float4*)(Q + (size_t)(b * Lr + q0 + r) * (H_C * D_C) + h * D_C + lid * 4);
    *(float4*)(Qs + r * FQ + lid * 4) = v;
  }

  float m_i[4], l_i[4], acc[4][8];
#pragma unroll
  for (int i = 0; i < 4; ++i) {
    m_i[i] = -1e30f; l_i[i] = 0.f;
#pragma unroll
    for (int j = 0; j < 8; ++j) acc[i][j] = 0.f;
  }
  __syncthreads();

  const float scale = 0.08838834764831845f;  // 1/sqrt(128)

  for (int kt = 0; kt <= qt; ++kt) {         // causal: skip fully-masked tiles
    const int k0 = kt * 64;
#pragma unroll
    for (int r = wid; r < 64; r += 8) {
      const size_t base = (size_t)(b * Lr + k0 + r) * (KV_C * D_C) + kv * D_C + lid * 4;
      *(float4*)(Ks + r * FQ + lid * 4) = *(const float4*)(Km + base);
      *(float4*)(Vs + r * FQ + lid * 4) = *(const float4*)(Vm + base);
    }
    __syncthreads();

    // ---- S = Q @ K^T ----
    float s[4][4];
#pragma unroll
    for (int i = 0; i < 4; ++i)
#pragma unroll
      for (int j = 0; j < 4; ++j) s[i][j] = 0.f;

#pragma unroll 2
    for (int d = 0; d < 128; d += 4) {
      float4 a[4], bb[4];
#pragma unroll
      for (int i = 0; i < 4; ++i) a[i]  = *(const float4*)(Qs + (rg + 16 * i) * FQ + d);
#pragma unroll
      for (int i = 0; i < 4; ++i) bb[i] = *(const float4*)(Ks + (cg + 16 * i) * FQ + d);
#pragma unroll
      for (int i = 0; i < 4; ++i)
#pragma unroll
        for (int j = 0; j < 4; ++j) {
          s[i][j] = fmaf(a[i].x, bb[j].x, s[i][j]);
          s[i][j] = fmaf(a[i].y, bb[j].y, s[i][j]);
          s[i][j] = fmaf(a[i].z, bb[j].z, s[i][j]);
          s[i][j] = fmaf(a[i].w, bb[j].w, s[i][j]);
        }
    }

    // ---- online softmax update ----
#pragma unroll
    for (int i = 0; i < 4; ++i) {
      const int qrow = rg + 16 * i;    // local row index
      float mx = -1e30f;
#pragma unroll
      for (int j = 0; j < 4; ++j) {
        float sv = s[i][j] * scale;
        if (kt == qt && (cg + 16 * j) > qrow) sv = -1e30f;  // causal mask on diagonal tile
        s[i][j] = sv;
        mx = fmaxf(mx, sv);
      }
#pragma unroll
      for (int o = 1; o < 16; o <<= 1) mx = fmaxf(mx, __shfl_xor_sync(0xffffffffu, mx, o));
      const float mn = fmaxf(m_i[i], mx);
      const float alpha = __expf(m_i[i] - mn);
      m_i[i] = mn;
      float rs = 0.f;
#pragma unroll
      for (int j = 0; j < 4; ++j) {
        const float p = __expf(s[i][j] - mn);
        s[i][j] = p;
        rs += p;
      }
#pragma unroll
      for (int o = 1; o < 16; o <<= 1) rs += __shfl_xor_sync(0xffffffffu, rs, o);
      l_i[i] = l_i[i] * alpha + rs;
#pragma unroll
      for (int j = 0; j < 8; ++j) acc[i][j] *= alpha;
#pragma unroll
      for (int j = 0; j < 4; ++j) Ps[qrow * FP + cg + 16 * j] = s[i][j];
    }
    __syncthreads();

    // ---- O += P @ V ----
#pragma unroll 2
    for (int kk = 0; kk < 64; kk += 4) {
      float4 p4[4];
#pragma unroll
      for (int i = 0; i < 4; ++i) p4[i] = *(const float4*)(Ps + (rg + 16 * i) * FP + kk);
#pragma unroll
      for (int u = 0; u < 4; ++u) {
        const float4 v0 = *(const float4*)(Vs + (kk + u) * FQ + cg * 8);
        const float4 v1 = *(const float4*)(Vs + (kk + u) * FQ + cg * 8 + 4);
#pragma unroll
        for (int i = 0; i < 4; ++i) {
          const float pv = ((const float*)&p4[i])[u];
          acc[i][0] = fmaf(pv, v0.x, acc[i][0]);
          acc[i][1] = fmaf(pv, v0.y, acc[i][1]);
          acc[i][2] = fmaf(pv, v0.z, acc[i][2]);
          acc[i][3] = fmaf(pv, v0.w, acc[i][3]);
          acc[i][4] = fmaf(pv, v1.x, acc[i][4]);
          acc[i][5] = fmaf(pv, v1.y, acc[i][5]);
          acc[i][6] = fmaf(pv, v1.z, acc[i][6]);
          acc[i][7] = fmaf(pv, v1.w, acc[i][7]);
        }
      }
    }
    __syncthreads();
  }

  // ---- normalize + write out ----
#pragma unroll
  for (int i = 0; i < 4; ++i) {
    const float inv = 1.f / l_i[i];
    float* op = O + (size_t)(b * Lr + q0 + rg + 16 * i) * (H_C * D_C) + h * D_C + cg * 8;
    float4 o0 = make_float4(acc[i][0] * inv, acc[i][1] * inv, acc[i][2] * inv, acc[i][3] * inv);
    float4 o1 = make_float4(acc[i][4] * inv, acc[i][5] * inv, acc[i][6] * inv, acc[i][7] * inv);
    *(float4*)op = o0;
    *(float4*)(op + 4) = o1;
  }
}

// ---------------------------------------------------------------------------
// kernel_launch
// inputs: x, cos, sin, wq, bq, wk, bk, wv, bv, wo
// ---------------------------------------------------------------------------
extern "C" void kernel_launch(void* const* d_in, const int* in_sizes, int n_in,
                              void* d_out, int out_size) {
  const float* x  = (const float*)d_in[0];
  const float* cs = (const float*)d_in[1];
  const float* sn = (const float*)d_in[2];
  const float* wq = (const float*)d_in[3];
  const float* bq = (const float*)d_in[4];
  const float* wk = (const float*)d_in[5];
  const float* bk = (const float*)d_in[6];
  const float* wv = (const float*)d_in[7];
  const float* bv = (const float*)d_in[8];
  const float* wo = (const float*)d_in[9];
  float* out = (float*)d_out;

  const int Lr = in_sizes[1] / 128;     // seq len (2048)
  const int Mr = in_sizes[0] / HID_C;   // B*L (4096)

  void *qp, *kp, *vp, *ap;
  cudaGetSymbolAddress(&qp, g_q);
  cudaGetSymbolAddress(&kp, g_k);
  cudaGetSymbolAddress(&vp, g_v);
  cudaGetSymbolAddress(&ap, g_attn);

  cudaFuncSetAttribute(gemm_nt<true>,  cudaFuncAttributeMaxDynamicSharedMemorySize, GEMM_SMEM);
  cudaFuncSetAttribute(gemm_nt<false>, cudaFuncAttributeMaxDynamicSharedMemorySize, GEMM_SMEM);
  cudaFuncSetAttribute(flash_kernel,   cudaFuncAttributeMaxDynamicSharedMemorySize, FLASH_SMEM);

  dim3 blk(256);

  // QKV projections
  dim3 gq(HID_C / BN, Mr / BM);            // (16, 32)
  gemm_nt<true><<<gq, blk, GEMM_SMEM>>>(x, wq, bq, (float*)qp, Mr, HID_C, HID_C);
  dim3 gkv((KV_C * D_C) / BN, Mr / BM);    // (2, 32)
  gemm_nt<true><<<gkv, blk, GEMM_SMEM>>>(x, wk, bk, (float*)kp, Mr, KV_C * D_C, HID_C);
  gemm_nt<true><<<gkv, blk, GEMM_SMEM>>>(x, wv, bv, (float*)vp, Mr, KV_C * D_C, HID_C);

  // RoPE on q and k (in place)
  const int rt = Mr * (H_C + KV_C) * 64;
  rope_kernel<<<(rt + 255) / 256, blk>>>((float*)qp, (float*)kp, cs, sn, Lr, Mr);

  // Flash attention
  dim3 gf(Lr / 64, H_C, Mr / Lr);          // (32, 16, 2)
  flash_kernel<<<gf, blk, FLASH_SMEM>>>((const float*)qp, (const float*)kp,
                                        (const float*)vp, (float*)ap, Lr);

  // Output projection
  gemm_nt<false><<<gq, blk, GEMM_SMEM>>>((const float*)ap, wo, nullptr, out, Mr, HID_C, HID_C);
}

// round 2
// speedup vs baseline: 1.7686x; 1.7686x over previous
#include <cuda_runtime.h>
#include <cuda_bf16.h>
#include <cstdint>

// ---------------------------------------------------------------------------
// Problem constants
// ---------------------------------------------------------------------------
constexpr int HID_C = 2048;
constexpr int H_C   = 16;
constexpr int KV_C  = 2;
constexpr int D_C   = 128;
constexpr int MAXM  = 4096;

// ---------------------------------------------------------------------------
// Scratch (static __device__; no allocation anywhere)
// ---------------------------------------------------------------------------
__device__ float g_q[MAXM * HID_C];
__device__ float g_k[MAXM * KV_C * D_C];
__device__ float g_v[MAXM * KV_C * D_C];
__device__ float g_attn[MAXM * HID_C];

__device__ __nv_bfloat16 g_xh[MAXM * HID_C],  g_xl[MAXM * HID_C];
__device__ __nv_bfloat16 g_wqh[HID_C * HID_C], g_wql[HID_C * HID_C];
__device__ __nv_bfloat16 g_wkh[KV_C * D_C * HID_C], g_wkl[KV_C * D_C * HID_C];
__device__ __nv_bfloat16 g_wvh[KV_C * D_C * HID_C], g_wvl[KV_C * D_C * HID_C];
__device__ __nv_bfloat16 g_woh[HID_C * HID_C], g_wol[HID_C * HID_C];
__device__ __nv_bfloat16 g_ah[MAXM * HID_C],  g_al[MAXM * HID_C];

// ---------------------------------------------------------------------------
// Helpers
// ---------------------------------------------------------------------------
__device__ __forceinline__ uint32_t smem_u32(const void* p) {
  return (uint32_t)__cvta_generic_to_shared(p);
}
__device__ __forceinline__ void cp_async16(uint32_t dst, const void* src) {
  asm volatile("cp.async.cg.shared.global [%0], [%1], 16;" :: "r"(dst), "l"(src));
}
__device__ __forceinline__ void cp_commit() { asm volatile("cp.async.commit_group;"); }
__device__ __forceinline__ void cp_wait1()  { asm volatile("cp.async.wait_group 1;"); }
__device__ __forceinline__ void cp_wait0()  { asm volatile("cp.async.wait_group 0;"); }

__device__ __forceinline__ void ldmx4(uint32_t (&r)[4], uint32_t addr) {
  asm volatile("ldmatrix.sync.aligned.m8n8.x4.shared.b16 {%0,%1,%2,%3}, [%4];"
               : "=r"(r[0]), "=r"(r[1]), "=r"(r[2]), "=r"(r[3]) : "r"(addr));
}
__device__ __forceinline__ void mma_bf16(float (&d)[4], const uint32_t (&a)[4],
                                         const uint32_t b0, const uint32_t b1) {
  asm volatile(
      "mma.sync.aligned.m16n8k16.row.col.f32.bf16.bf16.f32 "
      "{%0,%1,%2,%3}, {%4,%5,%6,%7}, {%8,%9}, {%0,%1,%2,%3};"
      : "+f"(d[0]), "+f"(d[1]), "+f"(d[2]), "+f"(d[3])
      : "r"(a[0]), "r"(a[1]), "r"(a[2]), "r"(a[3]), "r"(b0), "r"(b1));
}

// ---------------------------------------------------------------------------
// fp32 -> (bf16 hi, bf16 lo) split
// ---------------------------------------------------------------------------
__global__ void split_kernel(const float* __restrict__ s, __nv_bfloat16* __restrict__ hi,
                             __nv_bfloat16* __restrict__ lo, int n4) {
  int i = blockIdx.x * blockDim.x + threadIdx.x;
  if (i >= n4) return;
  float4 v = ((const float4*)s)[i];
  __nv_bfloat16 h[4], l[4];
  float f[4] = {v.x, v.y, v.z, v.w};
#pragma unroll
  for (int j = 0; j < 4; ++j) {
    h[j] = __float2bfloat16(f[j]);
    l[j] = __float2bfloat16(f[j] - __bfloat162float(h[j]));
  }
  ((uint2*)hi)[i] = *(uint2*)h;
  ((uint2*)lo)[i] = *(uint2*)l;
}

// ---------------------------------------------------------------------------
// bf16x3 split-precision NT GEMM (tensor cores)
// C[m,n] = sum_k (Ah+Al)[m,k]*(Bh+Bl)[n,k]  ~=  Ah*Bh + Ah*Bl + Al*Bh  (+bias)
// 128x128x32 tiles, cp.async double-buffered, ldmatrix.x4 fragments,
// 8 warps as 2(m) x 4(n), warp tile 64x32.
// ---------------------------------------------------------------------------
constexpr int LDAB = 40;                         // padded smem row, bf16 elems
constexpr int GTILE = 128 * LDAB;                // elems per operand buffer
constexpr int GTILE_B = GTILE * 2;               // bytes (10240)
constexpr int GEMM_SMEM = 8 * GTILE_B;           // 4 operands x 2 buffers = 81920

template <bool HAS_BIAS>
__global__ void __launch_bounds__(256, 1)
gemm_bf16x3(const __nv_bfloat16* __restrict__ Ah, const __nv_bfloat16* __restrict__ Al,
            const __nv_bfloat16* __restrict__ Bh, const __nv_bfloat16* __restrict__ Bl,
            const float* __restrict__ bias, float* __restrict__ C,
            int M, int N, int K) {
  extern __shared__ __nv_bfloat16 smb[];
  __nv_bfloat16* sAh = smb;
  __nv_bfloat16* sAl = smb + 2 * GTILE;
  __nv_bfloat16* sBh = smb + 4 * GTILE;
  __nv_bfloat16* sBl = smb + 6 * GTILE;

  const int tid = threadIdx.x;
  const int lane = tid & 31, wid = tid >> 5;
  const int wm = wid & 1, wn = wid >> 1;           // warp tile: (wm*64, wn*32)
  const int m0 = blockIdx.y * 128, n0 = blockIdx.x * 128;

  // cp.async mapping: thread -> rows (tid>>2) and (tid>>2)+64, 8 bf16 each
  const int lrow = tid >> 2;
  const int lcol = (tid & 3) * 8;
  const size_t aoff = (size_t)(m0 + lrow) * K + lcol;
  const size_t boff = (size_t)(n0 + lrow) * K + lcol;
  const uint32_t sdst = (uint32_t)((lrow * LDAB + lcol) * 2);
  const uint32_t sAh0 = smem_u32(sAh) + sdst;
  const uint32_t sAl0 = smem_u32(sAl) + sdst;
  const uint32_t sBh0 = smem_u32(sBh) + sdst;
  const uint32_t sBl0 = smem_u32(sBl) + sdst;
  constexpr uint32_t RSTEP = 64 * LDAB * 2;        // bytes for +64 rows

  const int KT = K / 32;

  auto load_tile = [&](int kt, int buf) {
    const size_t g = (size_t)kt * 32;
    const uint32_t so = (uint32_t)buf * GTILE_B;
    const size_t a2 = aoff + g, b2 = boff + g;
    cp_async16(sAh0 + so,         Ah + a2);
    cp_async16(sAh0 + so + RSTEP, Ah + a2 + (size_t)64 * K);
    cp_async16(sAl0 + so,         Al + a2);
    cp_async16(sAl0 + so + RSTEP, Al + a2 + (size_t)64 * K);
    cp_async16(sBh0 + so,         Bh + b2);
    cp_async16(sBh0 + so + RSTEP, Bh + b2 + (size_t)64 * K);
    cp_async16(sBl0 + so,         Bl + b2);
    cp_async16(sBl0 + so + RSTEP, Bl + b2 + (size_t)64 * K);
  };

  load_tile(0, 0);
  cp_commit();

  float acc[4][4][4];
#pragma unroll
  for (int i = 0; i < 4; ++i)
#pragma unroll
    for (int j = 0; j < 4; ++j)
#pragma unroll
      for (int r = 0; r < 4; ++r) acc[i][j][r] = 0.f;

  // ldmatrix source coordinates (within this warp's tile)
  const int arow = wm * 64 + (lane & 15);
  const int acolx = ((lane >> 4) << 3);            // +k2*16
  const int brow = wn * 32 + ((lane >> 4) << 3) + (lane & 7);
  const int bcolx = (((lane >> 3) & 1) << 3);      // +k2*16
  const uint32_t sAhB = smem_u32(sAh), sAlB = smem_u32(sAl);
  const uint32_t sBhB = smem_u32(sBh), sBlB = smem_u32(sBl);

  for (int kt = 0; kt < KT; ++kt) {
    const int buf = kt & 1;
    if (kt + 1 < KT) {
      load_tile(kt + 1, buf ^ 1);
      cp_commit();
      cp_wait1();
    } else {
      cp_wait0();
    }
    __syncthreads();

    const uint32_t so = (uint32_t)buf * GTILE_B;
#pragma unroll
    for (int k2 = 0; k2 < 2; ++k2) {
      uint32_t afh[4][4], afl[4][4], bfh[4][2], bfl[4][2];
      const uint32_t acol = k2 * 16 + acolx;
      const uint32_t bcol = k2 * 16 + bcolx;
#pragma unroll
      for (int mt = 0; mt < 4; ++mt) {
        const uint32_t ao = so + (uint32_t)(((arow + mt * 16) * LDAB + acol) * 2);
        ldmx4(afh[mt], sAhB + ao);
        ldmx4(afl[mt], sAlB + ao);
      }
#pragma unroll
      for (int nt2 = 0; nt2 < 2; ++nt2) {
        uint32_t t[4];
        const uint32_t bo = so + (uint32_t)(((brow + nt2 * 16) * LDAB + bcol) * 2);
        ldmx4(t, sBhB + bo);
        bfh[nt2 * 2][0] = t[0]; bfh[nt2 * 2][1] = t[1];
        bfh[nt2 * 2 + 1][0] = t[2]; bfh[nt2 * 2 + 1][1] = t[3];
        ldmx4(t, sBlB + bo);
        bfl[nt2 * 2][0] = t[0]; bfl[nt2 * 2][1] = t[1];
        bfl[nt2 * 2 + 1][0] = t[2]; bfl[nt2 * 2 + 1][1] = t[3];
      }
#pragma unroll
      for (int mt = 0; mt < 4; ++mt)
#pragma unroll
        for (int nt = 0; nt < 4; ++nt) {
          mma_bf16(acc[mt][nt], afh[mt], bfh[nt][0], bfh[nt][1]);
          mma_bf16(acc[mt][nt], afh[mt], bfl[nt][0], bfl[nt][1]);
          mma_bf16(acc[mt][nt], afl[mt], bfh[nt][0], bfh[nt][1]);
        }
    }
    __syncthreads();
  }

  // Epilogue
  float2 bv[4];
#pragma unroll
  for (int nt = 0; nt < 4; ++nt) {
    const int col = n0 + wn * 32 + nt * 8 + (lane & 3) * 2;
    if (HAS_BIAS) { bv[nt].x = bias[col]; bv[nt].y = bias[col + 1]; }
    else          { bv[nt].x = 0.f;       bv[nt].y = 0.f; }
  }
#pragma unroll
  for (int mt = 0; mt < 4; ++mt) {
    const int r0 = m0 + wm * 64 + mt * 16 + (lane >> 2);
#pragma unroll
    for (int nt = 0; nt < 4; ++nt) {
      const int col = n0 + wn * 32 + nt * 8 + (lane & 3) * 2;
      float2 v0 = make_float2(acc[mt][nt][0] + bv[nt].x, acc[mt][nt][1] + bv[nt].y);
      float2 v1 = make_float2(acc[mt][nt][2] + bv[nt].x, acc[mt][nt][3] + bv[nt].y);
      *(float2*)(C + (size_t)r0 * N + col) = v0;
      *(float2*)(C + (size_t)(r0 + 8) * N + col) = v1;
    }
  }
}

// ---------------------------------------------------------------------------
// RoPE (in-place on q and k)
// ---------------------------------------------------------------------------
__global__ void rope_kernel(float* __restrict__ q, float* __restrict__ k,
                            const float* __restrict__ cs, const float* __restrict__ sn,
                            int Lr, int Mr) {
  const int per = (H_C + KV_C) * 64;
  int t = blockIdx.x * blockDim.x + threadIdx.x;
  if (t >= Mr * per) return;
  int row = t / per;
  int rem = t - row * per;
  int hd = rem >> 6;
  int d = rem & 63;
  int l = row % Lr;
  float c = cs[l * 128 + d];
  float s = sn[l * 128 + d];
  float* p;
  if (hd < H_C) p = q + (size_t)row * (H_C * D_C) + hd * D_C;
  else          p = k + (size_t)row * (KV_C * D_C) + (hd - H_C) * D_C;
  float x1 = p[d], x2 = p[d + 64];
  p[d]      = x1 * c - x2 * s;
  p[d + 64] = x2 * c + x1 * s;
}

// ---------------------------------------------------------------------------
// Flash attention (fp32, causal, GQA) — unchanged from R1
// ---------------------------------------------------------------------------
constexpr int FQ = 132;
constexpr int FP = 80;
constexpr int FLASH_SMEM = (3 * 64 * FQ + 64 * FP) * 4;

__global__ void __launch_bounds__(256, 1)
flash_kernel(const float* __restrict__ Q, const float* __restrict__ Km,
             const float* __restrict__ Vm, float* __restrict__ O, int Lr) {
  extern __shared__ float sm[];
  float* Qs = sm;
  float* Ks = Qs + 64 * FQ;
  float* Vs = Ks + 64 * FQ;
  float* Ps = Vs + 64 * FQ;

  const int qt = blockIdx.x;
  const int h  = blockIdx.y;
  const int b  = blockIdx.z;
  const int kv = h >> 3;
  const int q0 = qt * 64;
  const int tid = threadIdx.x;
  const int rg = tid >> 4;
  const int cg = tid & 15;
  const int wid = tid >> 5, lid = tid & 31;

#pragma unroll
  for (int r = wid; r < 64; r += 8) {
    const float4 v = *(const float4*)(Q + (size_t)(b * Lr + q0 + r) * (H_C * D_C) + h * D_C + lid * 4);
    *(float4*)(Qs + r * FQ + lid * 4) = v;
  }

  float m_i[4], l_i[4], acc[4][8];
#pragma unroll
  for (int i = 0; i < 4; ++i) {
    m_i[i] = -1e30f; l_i[i] = 0.f;
#pragma unroll
    for (int j = 0; j < 8; ++j) acc[i][j] = 0.f;
  }
  __syncthreads();

  const float scale = 0.08838834764831845f;

  for (int kt = 0; kt <= qt; ++kt) {
    const int k0 = kt * 64;
#pragma unroll
    for (int r = wid; r < 64; r += 8) {
      const size_t base = (size_t)(b * Lr + k0 + r) * (KV_C * D_C) + kv * D_C + lid * 4;
      *(float4*)(Ks + r * FQ + lid * 4) = *(const float4*)(Km + base);
      *(float4*)(Vs + r * FQ + lid * 4) = *(const float4*)(Vm + base);
    }
    __syncthreads();

    float s[4][4];
#pragma unroll
    for (int i = 0; i < 4; ++i)
#pragma unroll
      for (int j = 0; j < 4; ++j) s[i][j] = 0.f;

#pragma unroll 2
    for (int d = 0; d < 128; d += 4) {
      float4 a[4], bb[4];
#pragma unroll
      for (int i = 0; i < 4; ++i) a[i]  = *(const float4*)(Qs + (rg + 16 * i) * FQ + d);
#pragma unroll
      for (int i = 0; i < 4; ++i) bb[i] = *(const float4*)(Ks + (cg + 16 * i) * FQ + d);
#pragma unroll
      for (int i = 0; i < 4; ++i)
#pragma unroll
        for (int j = 0; j < 4; ++j) {
          s[i][j] = fmaf(a[i].x, bb[j].x, s[i][j]);
          s[i][j] = fmaf(a[i].y, bb[j].y, s[i][j]);
          s[i][j] = fmaf(a[i].z, bb[j].z, s[i][j]);
          s[i][j] = fmaf(a[i].w, bb[j].w, s[i][j]);
        }
    }

#pragma unroll
    for (int i = 0; i < 4; ++i) {
      const int qrow = rg + 16 * i;
      float mx = -1e30f;
#pragma unroll
      for (int j = 0; j < 4; ++j) {
        float sv = s[i][j] * scale;
        if (kt == qt && (cg + 16 * j) > qrow) sv = -1e30f;
        s[i][j] = sv;
        mx = fmaxf(mx, sv);
      }
#pragma unroll
      for (int o = 1; o < 16; o <<= 1) mx = fmaxf(mx, __shfl_xor_sync(0xffffffffu, mx, o));
      const float mn = fmaxf(m_i[i], mx);
      const float alpha = __expf(m_i[i] - mn);
      m_i[i] = mn;
      float rs = 0.f;
#pragma unroll
      for (int j = 0; j < 4; ++j) {
        const float p = __expf(s[i][j] - mn);
        s[i][j] = p;
        rs += p;
      }
#pragma unroll
      for (int o = 1; o < 16; o <<= 1) rs += __shfl_xor_sync(0xffffffffu, rs, o);
      l_i[i] = l_i[i] * alpha + rs;
#pragma unroll
      for (int j = 0; j < 8; ++j) acc[i][j] *= alpha;
#pragma unroll
      for (int j = 0; j < 4; ++j) Ps[qrow * FP + cg + 16 * j] = s[i][j];
    }
    __syncthreads();

#pragma unroll 2
    for (int kk = 0; kk < 64; kk += 4) {
      float4 p4[4];
#pragma unroll
      for (int i = 0; i < 4; ++i) p4[i] = *(const float4*)(Ps + (rg + 16 * i) * FP + kk);
#pragma unroll
      for (int u = 0; u < 4; ++u) {
        const float4 v0 = *(const float4*)(Vs + (kk + u) * FQ + cg * 8);
        const float4 v1 = *(const float4*)(Vs + (kk + u) * FQ + cg * 8 + 4);
#pragma unroll
        for (int i = 0; i < 4; ++i) {
          const float pv = ((const float*)&p4[i])[u];
          acc[i][0] = fmaf(pv, v0.x, acc[i][0]);
          acc[i][1] = fmaf(pv, v0.y, acc[i][1]);
          acc[i][2] = fmaf(pv, v0.z, acc[i][2]);
          acc[i][3] = fmaf(pv, v0.w, acc[i][3]);
          acc[i][4] = fmaf(pv, v1.x, acc[i][4]);
          acc[i][5] = fmaf(pv, v1.y, acc[i][5]);
          acc[i][6] = fmaf(pv, v1.z, acc[i][6]);
          acc[i][7] = fmaf(pv, v1.w, acc[i][7]);
        }
      }
    }
    __syncthreads();
  }

#pragma unroll
  for (int i = 0; i < 4; ++i) {
    const float inv = 1.f / l_i[i];
    float* op = O + (size_t)(b * Lr + q0 + rg + 16 * i) * (H_C * D_C) + h * D_C + cg * 8;
    float4 o0 = make_float4(acc[i][0] * inv, acc[i][1] * inv, acc[i][2] * inv, acc[i][3] * inv);
    float4 o1 = make_float4(acc[i][4] * inv, acc[i][5] * inv, acc[i][6] * inv, acc[i][7] * inv);
    *(float4*)op = o0;
    *(float4*)(op + 4) = o1;
  }
}

// ---------------------------------------------------------------------------
// kernel_launch: x, cos, sin, wq, bq, wk, bk, wv, bv, wo
// ---------------------------------------------------------------------------
extern "C" void kernel_launch(void* const* d_in, const int* in_sizes, int n_in,
                              void* d_out, int out_size) {
  const float* x  = (const float*)d_in[0];
  const float* cs = (const float*)d_in[1];
  const float* sn = (const float*)d_in[2];
  const float* wq = (const float*)d_in[3];
  const float* bq = (const float*)d_in[4];
  const float* wk = (const float*)d_in[5];
  const float* bk = (const float*)d_in[6];
  const float* wv = (const float*)d_in[7];
  const float* bv = (const float*)d_in[8];
  const float* wo = (const float*)d_in[9];
  float* out = (float*)d_out;

  const int Lr = in_sizes[1] / 128;
  const int Mr = in_sizes[0] / HID_C;
  const int NKV = KV_C * D_C;

  void *qp, *kp, *vp, *ap;
  void *xh, *xl, *wqh, *wql, *wkh, *wkl, *wvh, *wvl, *woh, *wol, *ah, *al;
  cudaGetSymbolAddress(&qp, g_q);   cudaGetSymbolAddress(&kp, g_k);
  cudaGetSymbolAddress(&vp, g_v);   cudaGetSymbolAddress(&ap, g_attn);
  cudaGetSymbolAddress(&xh, g_xh);  cudaGetSymbolAddress(&xl, g_xl);
  cudaGetSymbolAddress(&wqh, g_wqh); cudaGetSymbolAddress(&wql, g_wql);
  cudaGetSymbolAddress(&wkh, g_wkh); cudaGetSymbolAddress(&wkl, g_wkl);
  cudaGetSymbolAddress(&wvh, g_wvh); cudaGetSymbolAddress(&wvl, g_wvl);
  cudaGetSymbolAddress(&woh, g_woh); cudaGetSymbolAddress(&wol, g_wol);
  cudaGetSymbolAddress(&ah, g_ah);  cudaGetSymbolAddress(&al, g_al);

  cudaFuncSetAttribute(gemm_bf16x3<true>,  cudaFuncAttributeMaxDynamicSharedMemorySize, GEMM_SMEM);
  cudaFuncSetAttribute(gemm_bf16x3<false>, cudaFuncAttributeMaxDynamicSharedMemorySize, GEMM_SMEM);
  cudaFuncSetAttribute(flash_kernel,       cudaFuncAttributeMaxDynamicSharedMemorySize, FLASH_SMEM);

  dim3 blk(256);

  // Split inputs into bf16 hi/lo
  auto split = [&](const float* src, void* hi, void* lo, int n) {
    int n4 = n / 4;
    split_kernel<<<(n4 + 255) / 256, blk>>>(src, (__nv_bfloat16*)hi, (__nv_bfloat16*)lo, n4);
  };
  split(x,  xh,  xl,  Mr * HID_C);
  split(wq, wqh, wql, HID_C * HID_C);
  split(wk, wkh, wkl, NKV * HID_C);
  split(wv, wvh, wvl, NKV * HID_C);
  split(wo, woh, wol, HID_C * HID_C);

  // QKV projections (tensor-core bf16x3)
  dim3 gq(HID_C / 128, Mr / 128);
  gemm_bf16x3<true><<<gq, blk, GEMM_SMEM>>>(
      (const __nv_bfloat16*)xh, (const __nv_bfloat16*)xl,
      (const __nv_bfloat16*)wqh, (const __nv_bfloat16*)wql,
      bq, (float*)qp, Mr, HID_C, HID_C);
  dim3 gkv(NKV / 128, Mr / 128);
  gemm_bf16x3<true><<<gkv, blk, GEMM_SMEM>>>(
      (const __nv_bfloat16*)xh, (const __nv_bfloat16*)xl,
      (const __nv_bfloat16*)wkh, (const __nv_bfloat16*)wkl,
      bk, (float*)kp, Mr, NKV, HID_C);
  gemm_bf16x3<true><<<gkv, blk, GEMM_SMEM>>>(
      (const __nv_bfloat16*)xh, (const __nv_bfloat16*)xl,
      (const __nv_bfloat16*)wvh, (const __nv_bfloat16*)wvl,
      bv, (float*)vp, Mr, NKV, HID_C);

  // RoPE
  const int rt = Mr * (H_C + KV_C) * 64;
  rope_kernel<<<(rt + 255) / 256, blk>>>((float*)qp, (float*)kp, cs, sn, Lr, Mr);

  // Flash attention
  dim3 gf(Lr / 64, H_C, Mr / Lr);
  flash_kernel<<<gf, blk, FLASH_SMEM>>>((const float*)qp, (const float*)kp,
                                        (const float*)vp, (float*)ap, Lr);

  // Output projection
  split((const float*)ap, ah, al, Mr * HID_C);
  gemm_bf16x3<false><<<gq, blk, GEMM_SMEM>>>(
      (const __nv_bfloat16*)ah, (const __nv_bfloat16*)al,
      (const __nv_bfloat16*)woh, (const __nv_bfloat16*)wol,
      nullptr, out, Mr, HID_C, HID_C);
}

// round 4
// speedup vs baseline: 2.4961x; 1.4113x over previous
#include <cuda_runtime.h>
#include <cuda_bf16.h>
#include <cstdint>

// ---------------------------------------------------------------------------
// Problem constants
// ---------------------------------------------------------------------------
constexpr int HID_C = 2048;
constexpr int H_C   = 16;
constexpr int KV_C  = 2;
constexpr int D_C   = 128;
constexpr int MAXM  = 4096;

// ---------------------------------------------------------------------------
// Scratch (static __device__; no allocation anywhere)
// ---------------------------------------------------------------------------
__device__ float g_q[MAXM * HID_C];
__device__ float g_k[MAXM * KV_C * D_C];
__device__ float g_v[MAXM * KV_C * D_C];

__device__ __nv_bfloat16 g_xh[MAXM * HID_C],  g_xl[MAXM * HID_C];
__device__ __nv_bfloat16 g_wqh[HID_C * HID_C], g_wql[HID_C * HID_C];
__device__ __nv_bfloat16 g_wkh[KV_C * D_C * HID_C], g_wkl[KV_C * D_C * HID_C];
__device__ __nv_bfloat16 g_wvh[KV_C * D_C * HID_C], g_wvl[KV_C * D_C * HID_C];
__device__ __nv_bfloat16 g_woh[HID_C * HID_C], g_wol[HID_C * HID_C];
__device__ __nv_bfloat16 g_ah[MAXM * HID_C],  g_al[MAXM * HID_C];

__device__ __nv_bfloat16 g_qh[MAXM * HID_C],       g_ql[MAXM * HID_C];
__device__ __nv_bfloat16 g_kh[MAXM * KV_C * D_C],  g_kl[MAXM * KV_C * D_C];
__device__ __nv_bfloat16 g_vh[MAXM * KV_C * D_C],  g_vl[MAXM * KV_C * D_C];

// ---------------------------------------------------------------------------
// Helpers
// ---------------------------------------------------------------------------
__device__ __forceinline__ uint32_t smem_u32(const void* p) {
  return (uint32_t)__cvta_generic_to_shared(p);
}
__device__ __forceinline__ void cp_async16(uint32_t dst, const void* src) {
  asm volatile("cp.async.cg.shared.global [%0], [%1], 16;" :: "r"(dst), "l"(src));
}
__device__ __forceinline__ void cp_commit() { asm volatile("cp.async.commit_group;"); }
__device__ __forceinline__ void cp_wait1()  { asm volatile("cp.async.wait_group 1;"); }
__device__ __forceinline__ void cp_wait0()  { asm volatile("cp.async.wait_group 0;"); }

__device__ __forceinline__ void ldmx4(uint32_t (&r)[4], uint32_t addr) {
  asm volatile("ldmatrix.sync.aligned.m8n8.x4.shared.b16 {%0,%1,%2,%3}, [%4];"
               : "=r"(r[0]), "=r"(r[1]), "=r"(r[2]), "=r"(r[3]) : "r"(addr));
}
__device__ __forceinline__ void ldmx4t(uint32_t (&r)[4], uint32_t addr) {
  asm volatile("ldmatrix.sync.aligned.m8n8.x4.trans.shared.b16 {%0,%1,%2,%3}, [%4];"
               : "=r"(r[0]), "=r"(r[1]), "=r"(r[2]), "=r"(r[3]) : "r"(addr));
}
__device__ __forceinline__ void mma_bf16(float (&d)[4], const uint32_t (&a)[4],
                                         const uint32_t b0, const uint32_t b1) {
  asm volatile(
      "mma.sync.aligned.m16n8k16.row.col.f32.bf16.bf16.f32 "
      "{%0,%1,%2,%3}, {%4,%5,%6,%7}, {%8,%9}, {%0,%1,%2,%3};"
      : "+f"(d[0]), "+f"(d[1]), "+f"(d[2]), "+f"(d[3])
      : "r"(a[0]), "r"(a[1]), "r"(a[2]), "r"(a[3]), "r"(b0), "r"(b1));
}

// ---------------------------------------------------------------------------
// fp32 -> (bf16 hi, bf16 lo) split
// ---------------------------------------------------------------------------
__global__ void split_kernel(const float* __restrict__ s, __nv_bfloat16* __restrict__ hi,
                             __nv_bfloat16* __restrict__ lo, int n4) {
  int i = blockIdx.x * blockDim.x + threadIdx.x;
  if (i >= n4) return;
  float4 v = ((const float4*)s)[i];
  __nv_bfloat16 h[4], l[4];
  float f[4] = {v.x, v.y, v.z, v.w};
#pragma unroll
  for (int j = 0; j < 4; ++j) {
    h[j] = __float2bfloat16(f[j]);
    l[j] = __float2bfloat16(f[j] - __bfloat162float(h[j]));
  }
  ((uint2*)hi)[i] = *(uint2*)h;
  ((uint2*)lo)[i] = *(uint2*)l;
}

// ---------------------------------------------------------------------------
// bf16x3 split-precision NT GEMM (tensor cores) — unchanged (passed R2)
// ---------------------------------------------------------------------------
constexpr int LDAB = 40;
constexpr int GTILE = 128 * LDAB;
constexpr int GTILE_B = GTILE * 2;
constexpr int GEMM_SMEM = 8 * GTILE_B;

template <bool HAS_BIAS>
__global__ void __launch_bounds__(256, 1)
gemm_bf16x3(const __nv_bfloat16* __restrict__ Ah, const __nv_bfloat16* __restrict__ Al,
            const __nv_bfloat16* __restrict__ Bh, const __nv_bfloat16* __restrict__ Bl,
            const float* __restrict__ bias, float* __restrict__ C,
            int M, int N, int K) {
  extern __shared__ __nv_bfloat16 smb[];
  __nv_bfloat16* sAh = smb;
  __nv_bfloat16* sAl = smb + 2 * GTILE;
  __nv_bfloat16* sBh = smb + 4 * GTILE;
  __nv_bfloat16* sBl = smb + 6 * GTILE;

  const int tid = threadIdx.x;
  const int lane = tid & 31, wid = tid >> 5;
  const int wm = wid & 1, wn = wid >> 1;
  const int m0 = blockIdx.y * 128, n0 = blockIdx.x * 128;

  const int lrow = tid >> 2;
  const int lcol = (tid & 3) * 8;
  const size_t aoff = (size_t)(m0 + lrow) * K + lcol;
  const size_t boff = (size_t)(n0 + lrow) * K + lcol;
  const uint32_t sdst = (uint32_t)((lrow * LDAB + lcol) * 2);
  const uint32_t sAh0 = smem_u32(sAh) + sdst;
  const uint32_t sAl0 = smem_u32(sAl) + sdst;
  const uint32_t sBh0 = smem_u32(sBh) + sdst;
  const uint32_t sBl0 = smem_u32(sBl) + sdst;
  constexpr uint32_t RSTEP = 64 * LDAB * 2;

  const int KT = K / 32;

  auto load_tile = [&](int kt, int buf) {
    const size_t g = (size_t)kt * 32;
    const uint32_t so = (uint32_t)buf * GTILE_B;
    const size_t a2 = aoff + g, b2 = boff + g;
    cp_async16(sAh0 + so,         Ah + a2);
    cp_async16(sAh0 + so + RSTEP, Ah + a2 + (size_t)64 * K);
    cp_async16(sAl0 + so,         Al + a2);
    cp_async16(sAl0 + so + RSTEP, Al + a2 + (size_t)64 * K);
    cp_async16(sBh0 + so,         Bh + b2);
    cp_async16(sBh0 + so + RSTEP, Bh + b2 + (size_t)64 * K);
    cp_async16(sBl0 + so,         Bl + b2);
    cp_async16(sBl0 + so + RSTEP, Bl + b2 + (size_t)64 * K);
  };

  load_tile(0, 0);
  cp_commit();

  float acc[4][4][4];
#pragma unroll
  for (int i = 0; i < 4; ++i)
#pragma unroll
    for (int j = 0; j < 4; ++j)
#pragma unroll
      for (int r = 0; r < 4; ++r) acc[i][j][r] = 0.f;

  const int arow = wm * 64 + (lane & 15);
  const int acolx = ((lane >> 4) << 3);
  const int brow = wn * 32 + ((lane >> 4) << 3) + (lane & 7);
  const int bcolx = (((lane >> 3) & 1) << 3);
  const uint32_t sAhB = smem_u32(sAh), sAlB = smem_u32(sAl);
  const uint32_t sBhB = smem_u32(sBh), sBlB = smem_u32(sBl);

  for (int kt = 0; kt < KT; ++kt) {
    const int buf = kt & 1;
    if (kt + 1 < KT) {
      load_tile(kt + 1, buf ^ 1);
      cp_commit();
      cp_wait1();
    } else {
      cp_wait0();
    }
    __syncthreads();

    const uint32_t so = (uint32_t)buf * GTILE_B;
#pragma unroll
    for (int k2 = 0; k2 < 2; ++k2) {
      uint32_t afh[4][4], afl[4][4], bfh[4][2], bfl[4][2];
      const uint32_t acol = k2 * 16 + acolx;
      const uint32_t bcol = k2 * 16 + bcolx;
#pragma unroll
      for (int mt = 0; mt < 4; ++mt) {
        const uint32_t ao = so + (uint32_t)(((arow + mt * 16) * LDAB + acol) * 2);
        ldmx4(afh[mt], sAhB + ao);
        ldmx4(afl[mt], sAlB + ao);
      }
#pragma unroll
      for (int nt2 = 0; nt2 < 2; ++nt2) {
        uint32_t t[4];
        const uint32_t bo = so + (uint32_t)(((brow + nt2 * 16) * LDAB + bcol) * 2);
        ldmx4(t, sBhB + bo);
        bfh[nt2 * 2][0] = t[0]; bfh[nt2 * 2][1] = t[1];
        bfh[nt2 * 2 + 1][0] = t[2]; bfh[nt2 * 2 + 1][1] = t[3];
        ldmx4(t, sBlB + bo);
        bfl[nt2 * 2][0] = t[0]; bfl[nt2 * 2][1] = t[1];
        bfl[nt2 * 2 + 1][0] = t[2]; bfl[nt2 * 2 + 1][1] = t[3];
      }
#pragma unroll
      for (int mt = 0; mt < 4; ++mt)
#pragma unroll
        for (int nt = 0; nt < 4; ++nt) {
          mma_bf16(acc[mt][nt], afh[mt], bfh[nt][0], bfh[nt][1]);
          mma_bf16(acc[mt][nt], afh[mt], bfl[nt][0], bfl[nt][1]);
          mma_bf16(acc[mt][nt], afl[mt], bfh[nt][0], bfh[nt][1]);
        }
    }
    __syncthreads();
  }

  float2 bv[4];
#pragma unroll
  for (int nt = 0; nt < 4; ++nt) {
    const int col = n0 + wn * 32 + nt * 8 + (lane & 3) * 2;
    if (HAS_BIAS) { bv[nt].x = bias[col]; bv[nt].y = bias[col + 1]; }
    else          { bv[nt].x = 0.f;       bv[nt].y = 0.f; }
  }
#pragma unroll
  for (int mt = 0; mt < 4; ++mt) {
    const int r0 = m0 + wm * 64 + mt * 16 + (lane >> 2);
#pragma unroll
    for (int nt = 0; nt < 4; ++nt) {
      const int col = n0 + wn * 32 + nt * 8 + (lane & 3) * 2;
      float2 v0 = make_float2(acc[mt][nt][0] + bv[nt].x, acc[mt][nt][1] + bv[nt].y);
      float2 v1 = make_float2(acc[mt][nt][2] + bv[nt].x, acc[mt][nt][3] + bv[nt].y);
      *(float2*)(C + (size_t)r0 * N + col) = v0;
      *(float2*)(C + (size_t)(r0 + 8) * N + col) = v1;
    }
  }
}

// ---------------------------------------------------------------------------
// RoPE + bf16 hi/lo split (fused)
// ---------------------------------------------------------------------------
__global__ void rope_split(const float* __restrict__ q, const float* __restrict__ k,
                           const float* __restrict__ cs, const float* __restrict__ sn,
                           __nv_bfloat16* __restrict__ qh, __nv_bfloat16* __restrict__ ql,
                           __nv_bfloat16* __restrict__ kh, __nv_bfloat16* __restrict__ kl,
                           int Lr, int Mr) {
  const int per = (H_C + KV_C) * 64;
  int t = blockIdx.x * blockDim.x + threadIdx.x;
  if (t >= Mr * per) return;
  int row = t / per;
  int rem = t - row * per;
  int hd = rem >> 6;
  int d = rem & 63;
  int l = row % Lr;
  float c = cs[l * 128 + d];
  float s = sn[l * 128 + d];
  size_t base;
  const float* p;
  __nv_bfloat16 *oh, *ol;
  if (hd < H_C) {
    base = (size_t)row * HID_C + hd * D_C;
    p = q + base; oh = qh + base; ol = ql + base;
  } else {
    base = (size_t)row * (KV_C * D_C) + (hd - H_C) * D_C;
    p = k + base; oh = kh + base; ol = kl + base;
  }
  float x1 = p[d], x2 = p[d + 64];
  float y1 = x1 * c - x2 * s;
  float y2 = x2 * c + x1 * s;
  __nv_bfloat16 h1 = __float2bfloat16(y1);
  __nv_bfloat16 h2 = __float2bfloat16(y2);
  oh[d]      = h1;  ol[d]      = __float2bfloat16(y1 - __bfloat162float(h1));
  oh[d + 64] = h2;  ol[d + 64] = __float2bfloat16(y2 - __bfloat162float(h2));
}

// ---------------------------------------------------------------------------
// Flash attention, bf16x3 MMA, 64x64 tiles, 8 warps (4m x 2n), causal, GQA.
// Cross-warp softmax stats combined via smem (full-row max/sum).
// ---------------------------------------------------------------------------
constexpr int LDK = 136;
constexpr int LDP = 72;
constexpr int SM_QH = 0;
constexpr int SM_QL = 1 * 64 * LDK;
constexpr int SM_KH = 2 * 64 * LDK;
constexpr int SM_KL = 3 * 64 * LDK;
constexpr int SM_VH = 4 * 64 * LDK;
constexpr int SM_VL = 5 * 64 * LDK;
constexpr int SM_PH = 6 * 64 * LDK;
constexpr int SM_PL = 6 * 64 * LDK + 64 * LDP;
constexpr int SM_RED = 6 * 64 * LDK + 2 * 64 * LDP;          // bf16 elems used
constexpr int FLASH2_SMEM = SM_RED * 2 + 2 * 128 * 4;        // + redm/reds floats

__global__ void __launch_bounds__(256, 1)
flash_mma(const __nv_bfloat16* __restrict__ Qh, const __nv_bfloat16* __restrict__ Ql,
          const __nv_bfloat16* __restrict__ Kh, const __nv_bfloat16* __restrict__ Kl,
          const __nv_bfloat16* __restrict__ Vh, const __nv_bfloat16* __restrict__ Vl,
          __nv_bfloat16* __restrict__ Oh, __nv_bfloat16* __restrict__ Ol, int Lr) {
  extern __shared__ __nv_bfloat16 sb[];
  const uint32_t sbase = smem_u32(sb);
  float* redm = (float*)(sb + SM_RED);        // [2][64] partial row max
  float* reds = redm + 128;                   // [2][64] partial row sum

  const int qt = blockIdx.x, h = blockIdx.y, b = blockIdx.z;
  const int kvh = h >> 3;
  const int q0 = qt * 64;
  const int tid = threadIdx.x, lane = tid & 31, w = tid >> 5;
  const int wm = w & 3, wn = w >> 2;

  const int lr = tid & 63, lcg = tid >> 6;

  // ---- Q tile (loaded once) ----
  {
    const size_t grow = (size_t)(b * Lr + q0 + lr) * HID_C + h * D_C + lcg * 32;
    const uint32_t sd = (uint32_t)((lr * LDK + lcg * 32) * 2);
#pragma unroll
    for (int i = 0; i < 4; ++i) {
      cp_async16(sbase + SM_QH * 2 + sd + i * 16, Qh + grow + i * 8);
      cp_async16(sbase + SM_QL * 2 + sd + i * 16, Ql + grow + i * 8);
    }
    cp_commit();
  }

  const int rq = lane >> 2, tq = lane & 3;
  const int arow = wm * 16 + (lane & 15);
  const int kcol8 = (lane >> 4) << 3;
  const int brow = wn * 32 + kcol8 + (lane & 7);
  const int bcol8 = ((lane >> 3) & 1) << 3;
  const int vrow = lane & 15;
  const int row0 = wm * 16 + rq;              // this thread's first q row (local)

  float m0 = -1e30f, m1 = -1e30f, l0 = 0.f, l1 = 0.f;
  float oacc[8][4];
#pragma unroll
  for (int i = 0; i < 8; ++i)
#pragma unroll
    for (int j = 0; j < 4; ++j) oacc[i][j] = 0.f;

  const float scale = 0.08838834764831845f;

  for (int kt = 0; kt <= qt; ++kt) {
    const int k0 = kt * 64;
    __syncthreads();
    {
      const size_t gr = (size_t)(b * Lr + k0 + lr) * (KV_C * D_C) + kvh * D_C + lcg * 32;
      const uint32_t sd = (uint32_t)((lr * LDK + lcg * 32) * 2);
#pragma unroll
      for (int i = 0; i < 4; ++i) {
        cp_async16(sbase + SM_KH * 2 + sd + i * 16, Kh + gr + i * 8);
        cp_async16(sbase + SM_KL * 2 + sd + i * 16, Kl + gr + i * 8);
        cp_async16(sbase + SM_VH * 2 + sd + i * 16, Vh + gr + i * 8);
        cp_async16(sbase + SM_VL * 2 + sd + i * 16, Vl + gr + i * 8);
      }
      cp_commit();
    }
    cp_wait0();
    __syncthreads();

    // ---- S = Q K^T (3-term bf16x3) ----
    float sa[4][4];
#pragma unroll
    for (int i = 0; i < 4; ++i)
#pragma unroll
      for (int j = 0; j < 4; ++j) sa[i][j] = 0.f;

#pragma unroll
    for (int kst = 0; kst < 8; ++kst) {
      uint32_t ah4[4], al4[4];
      const uint32_t ao = (uint32_t)((arow * LDK + kst * 16 + kcol8) * 2);
      ldmx4(ah4, sbase + SM_QH * 2 + ao);
      ldmx4(al4, sbase + SM_QL * 2 + ao);
      uint32_t bh[4][2], bl[4][2];
#pragma unroll
      for (int nt2 = 0; nt2 < 2; ++nt2) {
        uint32_t t4[4];
        const uint32_t bo = (uint32_t)(((brow + nt2 * 16) * LDK + kst * 16 + bcol8) * 2);
        ldmx4(t4, sbase + SM_KH * 2 + bo);
        bh[nt2 * 2][0] = t4[0]; bh[nt2 * 2][1] = t4[1];
        bh[nt2 * 2 + 1][0] = t4[2]; bh[nt2 * 2 + 1][1] = t4[3];
        ldmx4(t4, sbase + SM_KL * 2 + bo);
        bl[nt2 * 2][0] = t4[0]; bl[nt2 * 2][1] = t4[1];
        bl[nt2 * 2 + 1][0] = t4[2]; bl[nt2 * 2 + 1][1] = t4[3];
      }
#pragma unroll
      for (int nf = 0; nf < 4; ++nf) {
        mma_bf16(sa[nf], ah4, bh[nf][0], bh[nf][1]);
        mma_bf16(sa[nf], ah4, bl[nf][0], bl[nf][1]);
        mma_bf16(sa[nf], al4, bh[nf][0], bh[nf][1]);
      }
    }

    // ---- scale + causal mask + partial row max (this warp's 32 cols) ----
    const bool diag = (kt == qt);
    float tmx0 = -1e30f, tmx1 = -1e30f;
#pragma unroll
    for (int nf = 0; nf < 4; ++nf) {
#pragma unroll
      for (int j = 0; j < 4; ++j) {
        float sv = sa[nf][j] * scale;
        if (diag) {
          const int col = wn * 32 + nf * 8 + 2 * tq + (j & 1);
          const int rowl = row0 + ((j >= 2) ? 8 : 0);
          if (col > rowl) sv = -1e30f;
        }
        sa[nf][j] = sv;
        if (j < 2) tmx0 = fmaxf(tmx0, sv); else tmx1 = fmaxf(tmx1, sv);
      }
    }
    tmx0 = fmaxf(tmx0, __shfl_xor_sync(0xffffffffu, tmx0, 1));
    tmx0 = fmaxf(tmx0, __shfl_xor_sync(0xffffffffu, tmx0, 2));
    tmx1 = fmaxf(tmx1, __shfl_xor_sync(0xffffffffu, tmx1, 1));
    tmx1 = fmaxf(tmx1, __shfl_xor_sync(0xffffffffu, tmx1, 2));
    if (tq == 0) {
      redm[wn * 64 + row0] = tmx0;
      redm[wn * 64 + row0 + 8] = tmx1;
    }
    __syncthreads();   // stats barrier A: partial maxes visible

    // ---- full-row max -> online softmax update ----
    const float fm0 = fmaxf(redm[row0], redm[64 + row0]);
    const float fm1 = fmaxf(redm[row0 + 8], redm[64 + row0 + 8]);
    const float mn0 = fmaxf(m0, fm0), mn1 = fmaxf(m1, fm1);
    const float al0 = __expf(m0 - mn0), al1 = __expf(m1 - mn1);
    m0 = mn0; m1 = mn1;

    float rs0 = 0.f, rs1 = 0.f;
#pragma unroll
    for (int nf = 0; nf < 4; ++nf) {
      float p0 = __expf(sa[nf][0] - mn0);
      float p1 = __expf(sa[nf][1] - mn0);
      float p2 = __expf(sa[nf][2] - mn1);
      float p3 = __expf(sa[nf][3] - mn1);
      rs0 += p0 + p1; rs1 += p2 + p3;
      sa[nf][0] = p0; sa[nf][1] = p1; sa[nf][2] = p2; sa[nf][3] = p3;
    }
    rs0 += __shfl_xor_sync(0xffffffffu, rs0, 1);
    rs0 += __shfl_xor_sync(0xffffffffu, rs0, 2);
    rs1 += __shfl_xor_sync(0xffffffffu, rs1, 1);
    rs1 += __shfl_xor_sync(0xffffffffu, rs1, 2);
    if (tq == 0) {
      reds[wn * 64 + row0] = rs0;
      reds[wn * 64 + row0 + 8] = rs1;
    }

#pragma unroll
    for (int nf = 0; nf < 8; ++nf) {
      oacc[nf][0] *= al0; oacc[nf][1] *= al0;
      oacc[nf][2] *= al1; oacc[nf][3] *= al1;
    }

    // ---- write P (bf16 hi/lo) to smem ----
#pragma unroll
    for (int nf = 0; nf < 4; ++nf) {
      const int pcol = wn * 32 + nf * 8 + 2 * tq;
      __nv_bfloat16 h0 = __float2bfloat16(sa[nf][0]);
      __nv_bfloat16 h1 = __float2bfloat16(sa[nf][1]);
      __nv_bfloat16 h2 = __float2bfloat16(sa[nf][2]);
      __nv_bfloat16 h3 = __float2bfloat16(sa[nf][3]);
      __nv_bfloat162 ph01; ph01.x = h0; ph01.y = h1;
      __nv_bfloat162 ph23; ph23.x = h2; ph23.y = h3;
      __nv_bfloat162 pl01, pl23;
      pl01.x = __float2bfloat16(sa[nf][0] - __bfloat162float(h0));
      pl01.y = __float2bfloat16(sa[nf][1] - __bfloat162float(h1));
      pl23.x = __float2bfloat16(sa[nf][2] - __bfloat162float(h2));
      pl23.y = __float2bfloat16(sa[nf][3] - __bfloat162float(h3));
      *(__nv_bfloat162*)(sb + SM_PH + row0 * LDP + pcol) = ph01;
      *(__nv_bfloat162*)(sb + SM_PH + (row0 + 8) * LDP + pcol) = ph23;
      *(__nv_bfloat162*)(sb + SM_PL + row0 * LDP + pcol) = pl01;
      *(__nv_bfloat162*)(sb + SM_PL + (row0 + 8) * LDP + pcol) = pl23;
    }
    __syncthreads();   // stats barrier B: P + partial sums visible

    // ---- full-row sum -> l update ----
    l0 = l0 * al0 + (reds[row0] + reds[64 + row0]);
    l1 = l1 * al1 + (reds[row0 + 8] + reds[64 + row0 + 8]);

    // ---- O += P V (3-term bf16x3, V via ldmatrix.trans) ----
#pragma unroll
    for (int k0i = 0; k0i < 64; k0i += 16) {
      uint32_t pah[4], pal[4];
      const uint32_t po = (uint32_t)((arow * LDP + k0i + kcol8) * 2);
      ldmx4(pah, sbase + SM_PH * 2 + po);
      ldmx4(pal, sbase + SM_PL * 2 + po);
#pragma unroll
      for (int df = 0; df < 4; ++df) {
        uint32_t th[4], tl[4];
        const uint32_t bo = (uint32_t)(((k0i + vrow) * LDK + wn * 64 + df * 16 + kcol8) * 2);
        ldmx4t(th, sbase + SM_VH * 2 + bo);
        ldmx4t(tl, sbase + SM_VL * 2 + bo);
        mma_bf16(oacc[df * 2],     pah, th[0], th[1]);
        mma_bf16(oacc[df * 2],     pah, tl[0], tl[1]);
        mma_bf16(oacc[df * 2],     pal, th[0], th[1]);
        mma_bf16(oacc[df * 2 + 1], pah, th[2], th[3]);
        mma_bf16(oacc[df * 2 + 1], pah, tl[2], tl[3]);
        mma_bf16(oacc[df * 2 + 1], pal, th[2], th[3]);
      }
    }
  }

  // ---- normalize + write bf16 hi/lo output ----
  const float inv0 = 1.f / l0, inv1 = 1.f / l1;
  const size_t gr0 = (size_t)(b * Lr + q0 + row0) * HID_C;
  const size_t gr1 = gr0 + (size_t)8 * HID_C;
#pragma unroll
  for (int nf = 0; nf < 8; ++nf) {
    const int col = h * D_C + wn * 64 + nf * 8 + 2 * tq;
    float o0 = oacc[nf][0] * inv0, o1 = oacc[nf][1] * inv0;
    float o2 = oacc[nf][2] * inv1, o3 = oacc[nf][3] * inv1;
    __nv_bfloat162 h01, h23, l01, l23;
    h01.x = __float2bfloat16(o0); h01.y = __float2bfloat16(o1);
    h23.x = __float2bfloat16(o2); h23.y = __float2bfloat16(o3);
    l01.x = __float2bfloat16(o0 - __bfloat162float(h01.x));
    l01.y = __float2bfloat16(o1 - __bfloat162float(h01.y));
    l23.x = __float2bfloat16(o2 - __bfloat162float(h23.x));
    l23.y = __float2bfloat16(o3 - __bfloat162float(h23.y));
    *(__nv_bfloat162*)(Oh + gr0 + col) = h01;
    *(__nv_bfloat162*)(Oh + gr1 + col) = h23;
    *(__nv_bfloat162*)(Ol + gr0 + col) = l01;
    *(__nv_bfloat162*)(Ol + gr1 + col) = l23;
  }
}

// ---------------------------------------------------------------------------
// kernel_launch: x, cos, sin, wq, bq, wk, bk, wv, bv, wo
// ---------------------------------------------------------------------------
extern "C" void kernel_launch(void* const* d_in, const int* in_sizes, int n_in,
                              void* d_out, int out_size) {
  const float* x  = (const float*)d_in[0];
  const float* cs = (const float*)d_in[1];
  const float* sn = (const float*)d_in[2];
  const float* wq = (const float*)d_in[3];
  const float* bq = (const float*)d_in[4];
  const float* wk = (const float*)d_in[5];
  const float* bk = (const float*)d_in[6];
  const float* wv = (const float*)d_in[7];
  const float* bv = (const float*)d_in[8];
  const float* wo = (const float*)d_in[9];
  float* out = (float*)d_out;

  const int Lr = in_sizes[1] / 128;
  const int Mr = in_sizes[0] / HID_C;
  const int NKV = KV_C * D_C;

  void *qp, *kp, *vp;
  void *xh, *xl, *wqh, *wql, *wkh, *wkl, *wvh, *wvl, *woh, *wol, *ah, *al;
  void *qhp, *qlp, *khp, *klp, *vhp, *vlp;
  cudaGetSymbolAddress(&qp, g_q);   cudaGetSymbolAddress(&kp, g_k);
  cudaGetSymbolAddress(&vp, g_v);
  cudaGetSymbolAddress(&xh, g_xh);  cudaGetSymbolAddress(&xl, g_xl);
  cudaGetSymbolAddress(&wqh, g_wqh); cudaGetSymbolAddress(&wql, g_wql);
  cudaGetSymbolAddress(&wkh, g_wkh); cudaGetSymbolAddress(&wkl, g_wkl);
  cudaGetSymbolAddress(&wvh, g_wvh); cudaGetSymbolAddress(&wvl, g_wvl);
  cudaGetSymbolAddress(&woh, g_woh); cudaGetSymbolAddress(&wol, g_wol);
  cudaGetSymbolAddress(&ah, g_ah);  cudaGetSymbolAddress(&al, g_al);
  cudaGetSymbolAddress(&qhp, g_qh); cudaGetSymbolAddress(&qlp, g_ql);
  cudaGetSymbolAddress(&khp, g_kh); cudaGetSymbolAddress(&klp, g_kl);
  cudaGetSymbolAddress(&vhp, g_vh); cudaGetSymbolAddress(&vlp, g_vl);

  cudaFuncSetAttribute(gemm_bf16x3<true>,  cudaFuncAttributeMaxDynamicSharedMemorySize, GEMM_SMEM);
  cudaFuncSetAttribute(gemm_bf16x3<false>, cudaFuncAttributeMaxDynamicSharedMemorySize, GEMM_SMEM);
  cudaFuncSetAttribute(flash_mma,          cudaFuncAttributeMaxDynamicSharedMemorySize, FLASH2_SMEM);

  dim3 blk(256);

  auto split = [&](const float* src, void* hi, void* lo, int n) {
    int n4 = n / 4;
    split_kernel<<<(n4 + 255) / 256, blk>>>(src, (__nv_bfloat16*)hi, (__nv_bfloat16*)lo, n4);
  };
  split(x,  xh,  xl,  Mr * HID_C);
  split(wq, wqh, wql, HID_C * HID_C);
  split(wk, wkh, wkl, NKV * HID_C);
  split(wv, wvh, wvl, NKV * HID_C);
  split(wo, woh, wol, HID_C * HID_C);

  // QKV projections
  dim3 gq(HID_C / 128, Mr / 128);
  gemm_bf16x3<true><<<gq, blk, GEMM_SMEM>>>(
      (const __nv_bfloat16*)xh, (const __nv_bfloat16*)xl,
      (const __nv_bfloat16*)wqh, (const __nv_bfloat16*)wql,
      bq, (float*)qp, Mr, HID_C, HID_C);
  dim3 gkv(NKV / 128, Mr / 128);
  gemm_bf16x3<true><<<gkv, blk, GEMM_SMEM>>>(
      (const __nv_bfloat16*)xh, (const __nv_bfloat16*)xl,
      (const __nv_bfloat16*)wkh, (const __nv_bfloat16*)wkl,
      bk, (float*)kp, Mr, NKV, HID_C);
  gemm_bf16x3<true><<<gkv, blk, GEMM_SMEM>>>(
      (const __nv_bfloat16*)xh, (const __nv_bfloat16*)xl,
      (const __nv_bfloat16*)wvh, (const __nv_bfloat16*)wvl,
      bv, (float*)vp, Mr, NKV, HID_C);

  // RoPE + split q,k ; split v
  const int rt = Mr * (H_C + KV_C) * 64;
  rope_split<<<(rt + 255) / 256, blk>>>((const float*)qp, (const float*)kp, cs, sn,
                                        (__nv_bfloat16*)qhp, (__nv_bfloat16*)qlp,
                                        (__nv_bfloat16*)khp, (__nv_bfloat16*)klp, Lr, Mr);
  split((const float*)vp, vhp, vlp, Mr * NKV);

  // Flash attention (tensor cores), writes bf16 hi/lo output
  dim3 gf(Lr / 64, H_C, Mr / Lr);
  flash_mma<<<gf, blk, FLASH2_SMEM>>>(
      (const __nv_bfloat16*)qhp, (const __nv_bfloat16*)qlp,
      (const __nv_bfloat16*)khp, (const __nv_bfloat16*)klp,
      (const __nv_bfloat16*)vhp, (const __nv_bfloat16*)vlp,
      (__nv_bfloat16*)ah, (__nv_bfloat16*)al, Lr);

  // Output projection
  gemm_bf16x3<false><<<gq, blk, GEMM_SMEM>>>(
      (const __nv_bfloat16*)ah, (const __nv_bfloat16*)al,
      (const __nv_bfloat16*)woh, (const __nv_bfloat16*)wol,
      nullptr, out, Mr, HID_C, HID_C);
}

// round 7
// speedup vs baseline: 2.6944x; 1.0794x over previous
#include <cuda_runtime.h>
#include <cuda_bf16.h>
#include <cstdint>

// ---------------------------------------------------------------------------
// Problem constants
// ---------------------------------------------------------------------------
constexpr int HID_C = 2048;
constexpr int H_C   = 16;
constexpr int KV_C  = 2;
constexpr int D_C   = 128;
constexpr int MAXM  = 4096;
constexpr int NCAT  = HID_C + 2 * KV_C * D_C;   // 2560 fused QKV output cols

// ---------------------------------------------------------------------------
// Scratch (static __device__; no allocation anywhere)
// ---------------------------------------------------------------------------
__device__ float g_qkv[MAXM * NCAT];             // fused QKV projection output
__device__ float g_bcat[NCAT];                   // concat bias

__device__ __nv_bfloat16 g_xh[MAXM * HID_C],  g_xl[MAXM * HID_C];
__device__ __nv_bfloat16 g_wcath[NCAT * HID_C], g_wcatl[NCAT * HID_C];
__device__ __nv_bfloat16 g_woh[HID_C * HID_C], g_wol[HID_C * HID_C];
__device__ __nv_bfloat16 g_ah[MAXM * HID_C],  g_al[MAXM * HID_C];

__device__ __nv_bfloat16 g_qh[MAXM * HID_C],       g_ql[MAXM * HID_C];
__device__ __nv_bfloat16 g_kh[MAXM * KV_C * D_C],  g_kl[MAXM * KV_C * D_C];
__device__ __nv_bfloat16 g_vh[MAXM * KV_C * D_C],  g_vl[MAXM * KV_C * D_C];

// ---------------------------------------------------------------------------
// Helpers
// ---------------------------------------------------------------------------
__device__ __forceinline__ uint32_t smem_u32(const void* p) {
  return (uint32_t)__cvta_generic_to_shared(p);
}
__device__ __forceinline__ void cp_async16(uint32_t dst, const void* src) {
  asm volatile("cp.async.cg.shared.global [%0], [%1], 16;" :: "r"(dst), "l"(src));
}
__device__ __forceinline__ void cp_commit() { asm volatile("cp.async.commit_group;"); }
__device__ __forceinline__ void cp_wait1()  { asm volatile("cp.async.wait_group 1;"); }
__device__ __forceinline__ void cp_wait0()  { asm volatile("cp.async.wait_group 0;"); }

__device__ __forceinline__ void ldmx4(uint32_t (&r)[4], uint32_t addr) {
  asm volatile("ldmatrix.sync.aligned.m8n8.x4.shared.b16 {%0,%1,%2,%3}, [%4];"
               : "=r"(r[0]), "=r"(r[1]), "=r"(r[2]), "=r"(r[3]) : "r"(addr));
}
__device__ __forceinline__ void ldmx4t(uint32_t (&r)[4], uint32_t addr) {
  asm volatile("ldmatrix.sync.aligned.m8n8.x4.trans.shared.b16 {%0,%1,%2,%3}, [%4];"
               : "=r"(r[0]), "=r"(r[1]), "=r"(r[2]), "=r"(r[3]) : "r"(addr));
}
__device__ __forceinline__ void mma_bf16(float (&d)[4], const uint32_t (&a)[4],
                                         const uint32_t b0, const uint32_t b1) {
  asm volatile(
      "mma.sync.aligned.m16n8k16.row.col.f32.bf16.bf16.f32 "
      "{%0,%1,%2,%3}, {%4,%5,%6,%7}, {%8,%9}, {%0,%1,%2,%3};"
      : "+f"(d[0]), "+f"(d[1]), "+f"(d[2]), "+f"(d[3])
      : "r"(a[0]), "r"(a[1]), "r"(a[2]), "r"(a[3]), "r"(b0), "r"(b1));
}

// ---------------------------------------------------------------------------
// Small kernels: bias concat, fp32 -> bf16 hi/lo split (plain + strided)
// ---------------------------------------------------------------------------
__global__ void bias_concat(const float* __restrict__ bq, const float* __restrict__ bk,
                            const float* __restrict__ bv, float* __restrict__ bc) {
  int i = blockIdx.x * blockDim.x + threadIdx.x;
  if (i >= NCAT) return;
  float v;
  if (i < HID_C) v = bq[i];
  else if (i < HID_C + KV_C * D_C) v = bk[i - HID_C];
  else v = bv[i - HID_C - KV_C * D_C];
  bc[i] = v;
}

__global__ void split_kernel(const float* __restrict__ s, __nv_bfloat16* __restrict__ hi,
                             __nv_bfloat16* __restrict__ lo, int n4) {
  int i = blockIdx.x * blockDim.x + threadIdx.x;
  if (i >= n4) return;
  float4 v = ((const float4*)s)[i];
  __nv_bfloat16 h[4], l[4];
  float f[4] = {v.x, v.y, v.z, v.w};
#pragma unroll
  for (int j = 0; j < 4; ++j) {
    h[j] = __float2bfloat16(f[j]);
    l[j] = __float2bfloat16(f[j] - __bfloat162float(h[j]));
  }
  ((uint2*)hi)[i] = *(uint2*)h;
  ((uint2*)lo)[i] = *(uint2*)l;
}

// Split V columns [2304, 2560) out of the fused QKV output into packed [M][256].
__global__ void split_v_strided(const float* __restrict__ qkv,
                                __nv_bfloat16* __restrict__ hi,
                                __nv_bfloat16* __restrict__ lo, int n4) {
  int i = blockIdx.x * blockDim.x + threadIdx.x;
  if (i >= n4) return;                   // n4 = M*64 (64 float4s per row)
  int row = i >> 6, c4 = i & 63;
  float4 v = *(const float4*)(qkv + (size_t)row * NCAT + (HID_C + KV_C * D_C) + c4 * 4);
  __nv_bfloat16 h[4], l[4];
  float f[4] = {v.x, v.y, v.z, v.w};
#pragma unroll
  for (int j = 0; j < 4; ++j) {
    h[j] = __float2bfloat16(f[j]);
    l[j] = __float2bfloat16(f[j] - __bfloat162float(h[j]));
  }
  ((uint2*)hi)[i] = *(uint2*)h;
  ((uint2*)lo)[i] = *(uint2*)l;
}

// ---------------------------------------------------------------------------
// bf16x3 split-precision NT GEMM (tensor cores) — proven in R2/R4
// ---------------------------------------------------------------------------
constexpr int LDAB = 40;
constexpr int GTILE = 128 * LDAB;
constexpr int GTILE_B = GTILE * 2;
constexpr int GEMM_SMEM = 8 * GTILE_B;

template <bool HAS_BIAS>
__global__ void __launch_bounds__(256, 1)
gemm_bf16x3(const __nv_bfloat16* __restrict__ Ah, const __nv_bfloat16* __restrict__ Al,
            const __nv_bfloat16* __restrict__ Bh, const __nv_bfloat16* __restrict__ Bl,
            const float* __restrict__ bias, float* __restrict__ C,
            int M, int N, int K) {
  extern __shared__ __nv_bfloat16 smb[];
  __nv_bfloat16* sAh = smb;
  __nv_bfloat16* sAl = smb + 2 * GTILE;
  __nv_bfloat16* sBh = smb + 4 * GTILE;
  __nv_bfloat16* sBl = smb + 6 * GTILE;

  const int tid = threadIdx.x;
  const int lane = tid & 31, wid = tid >> 5;
  const int wm = wid & 1, wn = wid >> 1;
  const int m0 = blockIdx.y * 128, n0 = blockIdx.x * 128;

  const int lrow = tid >> 2;
  const int lcol = (tid & 3) * 8;
  const size_t aoff = (size_t)(m0 + lrow) * K + lcol;
  const size_t boff = (size_t)(n0 + lrow) * K + lcol;
  const uint32_t sdst = (uint32_t)((lrow * LDAB + lcol) * 2);
  const uint32_t sAh0 = smem_u32(sAh) + sdst;
  const uint32_t sAl0 = smem_u32(sAl) + sdst;
  const uint32_t sBh0 = smem_u32(sBh) + sdst;
  const uint32_t sBl0 = smem_u32(sBl) + sdst;
  constexpr uint32_t RSTEP = 64 * LDAB * 2;

  const int KT = K / 32;

  auto load_tile = [&](int kt, int buf) {
    const size_t g = (size_t)kt * 32;
    const uint32_t so = (uint32_t)buf * GTILE_B;
    const size_t a2 = aoff + g, b2 = boff + g;
    cp_async16(sAh0 + so,         Ah + a2);
    cp_async16(sAh0 + so + RSTEP, Ah + a2 + (size_t)64 * K);
    cp_async16(sAl0 + so,         Al + a2);
    cp_async16(sAl0 + so + RSTEP, Al + a2 + (size_t)64 * K);
    cp_async16(sBh0 + so,         Bh + b2);
    cp_async16(sBh0 + so + RSTEP, Bh + b2 + (size_t)64 * K);
    cp_async16(sBl0 + so,         Bl + b2);
    cp_async16(sBl0 + so + RSTEP, Bl + b2 + (size_t)64 * K);
  };

  load_tile(0, 0);
  cp_commit();

  float acc[4][4][4];
#pragma unroll
  for (int i = 0; i < 4; ++i)
#pragma unroll
    for (int j = 0; j < 4; ++j)
#pragma unroll
      for (int r = 0; r < 4; ++r) acc[i][j][r] = 0.f;

  const int arow = wm * 64 + (lane & 15);
  const int acolx = ((lane >> 4) << 3);
  const int brow = wn * 32 + ((lane >> 4) << 3) + (lane & 7);
  const int bcolx = (((lane >> 3) & 1) << 3);
  const uint32_t sAhB = smem_u32(sAh), sAlB = smem_u32(sAl);
  const uint32_t sBhB = smem_u32(sBh), sBlB = smem_u32(sBl);

  for (int kt = 0; kt < KT; ++kt) {
    const int buf = kt & 1;
    if (kt + 1 < KT) {
      load_tile(kt + 1, buf ^ 1);
      cp_commit();
      cp_wait1();
    } else {
      cp_wait0();
    }
    __syncthreads();

    const uint32_t so = (uint32_t)buf * GTILE_B;
#pragma unroll
    for (int k2 = 0; k2 < 2; ++k2) {
      uint32_t afh[4][4], afl[4][4], bfh[4][2], bfl[4][2];
      const uint32_t acol = k2 * 16 + acolx;
      const uint32_t bcol = k2 * 16 + bcolx;
#pragma unroll
      for (int mt = 0; mt < 4; ++mt) {
        const uint32_t ao = so + (uint32_t)(((arow + mt * 16) * LDAB + acol) * 2);
        ldmx4(afh[mt], sAhB + ao);
        ldmx4(afl[mt], sAlB + ao);
      }
#pragma unroll
      for (int nt2 = 0; nt2 < 2; ++nt2) {
        uint32_t t[4];
        const uint32_t bo = so + (uint32_t)(((brow + nt2 * 16) * LDAB + bcol) * 2);
        ldmx4(t, sBhB + bo);
        bfh[nt2 * 2][0] = t[0]; bfh[nt2 * 2][1] = t[1];
        bfh[nt2 * 2 + 1][0] = t[2]; bfh[nt2 * 2 + 1][1] = t[3];
        ldmx4(t, sBlB + bo);
        bfl[nt2 * 2][0] = t[0]; bfl[nt2 * 2][1] = t[1];
        bfl[nt2 * 2 + 1][0] = t[2]; bfl[nt2 * 2 + 1][1] = t[3];
      }
#pragma unroll
      for (int mt = 0; mt < 4; ++mt)
#pragma unroll
        for (int nt = 0; nt < 4; ++nt) {
          mma_bf16(acc[mt][nt], afh[mt], bfh[nt][0], bfh[nt][1]);
          mma_bf16(acc[mt][nt], afh[mt], bfl[nt][0], bfl[nt][1]);
          mma_bf16(acc[mt][nt], afl[mt], bfh[nt][0], bfh[nt][1]);
        }
    }
    __syncthreads();
  }

  float2 bv[4];
#pragma unroll
  for (int nt = 0; nt < 4; ++nt) {
    const int col = n0 + wn * 32 + nt * 8 + (lane & 3) * 2;
    if (HAS_BIAS) { bv[nt].x = bias[col]; bv[nt].y = bias[col + 1]; }
    else          { bv[nt].x = 0.f;       bv[nt].y = 0.f; }
  }
#pragma unroll
  for (int mt = 0; mt < 4; ++mt) {
    const int r0 = m0 + wm * 64 + mt * 16 + (lane >> 2);
#pragma unroll
    for (int nt = 0; nt < 4; ++nt) {
      const int col = n0 + wn * 32 + nt * 8 + (lane & 3) * 2;
      float2 v0 = make_float2(acc[mt][nt][0] + bv[nt].x, acc[mt][nt][1] + bv[nt].y);
      float2 v1 = make_float2(acc[mt][nt][2] + bv[nt].x, acc[mt][nt][3] + bv[nt].y);
      *(float2*)(C + (size_t)r0 * N + col) = v0;
      *(float2*)(C + (size_t)(r0 + 8) * N + col) = v1;
    }
  }
}

// ---------------------------------------------------------------------------
// RoPE + bf16 hi/lo split (fused). Reads q,k from the fused QKV buffer
// ([M][2560], q at col 0, k at col 2048).
// ---------------------------------------------------------------------------
__global__ void rope_split(const float* __restrict__ qkv,
                           const float* __restrict__ cs, const float* __restrict__ sn,
                           __nv_bfloat16* __restrict__ qh, __nv_bfloat16* __restrict__ ql,
                           __nv_bfloat16* __restrict__ kh, __nv_bfloat16* __restrict__ kl,
                           int Lr, int Mr) {
  const int per = (H_C + KV_C) * 64;
  int t = blockIdx.x * blockDim.x + threadIdx.x;
  if (t >= Mr * per) return;
  int row = t / per;
  int rem = t - row * per;
  int hd = rem >> 6;
  int d = rem & 63;
  int l = row % Lr;
  float c = cs[l * 128 + d];
  float s = sn[l * 128 + d];
  const float* p;
  __nv_bfloat16 *oh, *ol;
  if (hd < H_C) {
    p  = qkv + (size_t)row * NCAT + hd * D_C;
    size_t ob = (size_t)row * HID_C + hd * D_C;
    oh = qh + ob; ol = ql + ob;
  } else {
    p  = qkv + (size_t)row * NCAT + HID_C + (hd - H_C) * D_C;
    size_t ob = (size_t)row * (KV_C * D_C) + (hd - H_C) * D_C;
    oh = kh + ob; ol = kl + ob;
  }
  float x1 = p[d], x2 = p[d + 64];
  float y1 = x1 * c - x2 * s;
  float y2 = x2 * c + x1 * s;
  __nv_bfloat16 h1 = __float2bfloat16(y1);
  __nv_bfloat16 h2 = __float2bfloat16(y2);
  oh[d]      = h1;  ol[d]      = __float2bfloat16(y1 - __bfloat162float(h1));
  oh[d + 64] = h2;  ol[d + 64] = __float2bfloat16(y2 - __bfloat162float(h2));
}

// ---------------------------------------------------------------------------
// Flash attention, bf16x3 MMA, 64x64 tiles, 8 warps (4m x 2n), causal, GQA.
// K and V in separate cp.async groups: V load overlaps S + softmax.
// ---------------------------------------------------------------------------
constexpr int LDK = 136;
constexpr int LDP = 72;
constexpr int SM_QH = 0;
constexpr int SM_QL = 1 * 64 * LDK;
constexpr int SM_KH = 2 * 64 * LDK;
constexpr int SM_KL = 3 * 64 * LDK;
constexpr int SM_VH = 4 * 64 * LDK;
constexpr int SM_VL = 5 * 64 * LDK;
constexpr int SM_PH = 6 * 64 * LDK;
constexpr int SM_PL = 6 * 64 * LDK + 64 * LDP;
constexpr int SM_RED = 6 * 64 * LDK + 2 * 64 * LDP;
constexpr int FLASH2_SMEM = SM_RED * 2 + 2 * 128 * 4;

__global__ void __launch_bounds__(256, 1)
flash_mma(const __nv_bfloat16* __restrict__ Qh, const __nv_bfloat16* __restrict__ Ql,
          const __nv_bfloat16* __restrict__ Kh, const __nv_bfloat16* __restrict__ Kl,
          const __nv_bfloat16* __restrict__ Vh, const __nv_bfloat16* __restrict__ Vl,
          __nv_bfloat16* __restrict__ Oh, __nv_bfloat16* __restrict__ Ol, int Lr) {
  extern __shared__ __nv_bfloat16 sb[];
  const uint32_t sbase = smem_u32(sb);
  float* redm = (float*)(sb + SM_RED);
  float* reds = redm + 128;

  const int qt = blockIdx.x, h = blockIdx.y, b = blockIdx.z;
  const int kvh = h >> 3;
  const int q0 = qt * 64;
  const int tid = threadIdx.x, lane = tid & 31, w = tid >> 5;
  const int wm = w & 3, wn = w >> 2;

  const int lr = tid & 63, lcg = tid >> 6;

  {
    const size_t grow = (size_t)(b * Lr + q0 + lr) * HID_C + h * D_C + lcg * 32;
    const uint32_t sd = (uint32_t)((lr * LDK + lcg * 32) * 2);
#pragma unroll
    for (int i = 0; i < 4; ++i) {
      cp_async16(sbase + SM_QH * 2 + sd + i * 16, Qh + grow + i * 8);
      cp_async16(sbase + SM_QL * 2 + sd + i * 16, Ql + grow + i * 8);
    }
    cp_commit();
  }

  const int rq = lane >> 2, tq = lane & 3;
  const int arow = wm * 16 + (lane & 15);
  const int kcol8 = (lane >> 4) << 3;
  const int brow = wn * 32 + kcol8 + (lane & 7);
  const int bcol8 = ((lane >> 3) & 1) << 3;
  const int vrow = lane & 15;
  const int row0 = wm * 16 + rq;

  float m0 = -1e30f, m1 = -1e30f, l0 = 0.f, l1 = 0.f;
  float oacc[8][4];
#pragma unroll
  for (int i = 0; i < 8; ++i)
#pragma unroll
    for (int j = 0; j < 4; ++j) oacc[i][j] = 0.f;

  const float scale = 0.08838834764831845f;

  for (int kt = 0; kt <= qt; ++kt) {
    const int k0 = kt * 64;
    __syncthreads();
    {
      const size_t gr = (size_t)(b * Lr + k0 + lr) * (KV_C * D_C) + kvh * D_C + lcg * 32;
      const uint32_t sd = (uint32_t)((lr * LDK + lcg * 32) * 2);
#pragma unroll
      for (int i = 0; i < 4; ++i) {
        cp_async16(sbase + SM_KH * 2 + sd + i * 16, Kh + gr + i * 8);
        cp_async16(sbase + SM_KL * 2 + sd + i * 16, Kl + gr + i * 8);
      }
      cp_commit();                       // K group
#pragma unroll
      for (int i = 0; i < 4; ++i) {
        cp_async16(sbase + SM_VH * 2 + sd + i * 16, Vh + gr + i * 8);
        cp_async16(sbase + SM_VL * 2 + sd + i * 16, Vl + gr + i * 8);
      }
      cp_commit();                       // V group
    }
    cp_wait1();                          // K (and Q) ready; V still in flight
    __syncthreads();

    float sa[4][4];
#pragma unroll
    for (int i = 0; i < 4; ++i)
#pragma unroll
      for (int j = 0; j < 4; ++j) sa[i][j] = 0.f;

#pragma unroll
    for (int kst = 0; kst < 8; ++kst) {
      uint32_t ah4[4], al4[4];
      const uint32_t ao = (uint32_t)((arow * LDK + kst * 16 + kcol8) * 2);
      ldmx4(ah4, sbase + SM_QH * 2 + ao);
      ldmx4(al4, sbase + SM_QL * 2 + ao);
      uint32_t bh[4][2], bl[4][2];
#pragma unroll
      for (int nt2 = 0; nt2 < 2; ++nt2) {
        uint32_t t4[4];
        const uint32_t bo = (uint32_t)(((brow + nt2 * 16) * LDK + kst * 16 + bcol8) * 2);
        ldmx4(t4, sbase + SM_KH * 2 + bo);
        bh[nt2 * 2][0] = t4[0]; bh[nt2 * 2][1] = t4[1];
        bh[nt2 * 2 + 1][0] = t4[2]; bh[nt2 * 2 + 1][1] = t4[3];
        ldmx4(t4, sbase + SM_KL * 2 + bo);
        bl[nt2 * 2][0] = t4[0]; bl[nt2 * 2][1] = t4[1];
        bl[nt2 * 2 + 1][0] = t4[2]; bl[nt2 * 2 + 1][1] = t4[3];
      }
#pragma unroll
      for (int nf = 0; nf < 4; ++nf) {
        mma_bf16(sa[nf], ah4, bh[nf][0], bh[nf][1]);
        mma_bf16(sa[nf], ah4, bl[nf][0], bl[nf][1]);
        mma_bf16(sa[nf], al4, bh[nf][0], bh[nf][1]);
      }
    }

    const bool diag = (kt == qt);
    float tmx0 = -1e30f, tmx1 = -1e30f;
#pragma unroll
    for (int nf = 0; nf < 4; ++nf) {
#pragma unroll
      for (int j = 0; j < 4; ++j) {
        float sv = sa[nf][j] * scale;
        if (diag) {
          const int col = wn * 32 + nf * 8 + 2 * tq + (j & 1);
          const int rowl = row0 + ((j >= 2) ? 8 : 0);
          if (col > rowl) sv = -1e30f;
        }
        sa[nf][j] = sv;
        if (j < 2) tmx0 = fmaxf(tmx0, sv); else tmx1 = fmaxf(tmx1, sv);
      }
    }
    tmx0 = fmaxf(tmx0, __shfl_xor_sync(0xffffffffu, tmx0, 1));
    tmx0 = fmaxf(tmx0, __shfl_xor_sync(0xffffffffu, tmx0, 2));
    tmx1 = fmaxf(tmx1, __shfl_xor_sync(0xffffffffu, tmx1, 1));
    tmx1 = fmaxf(tmx1, __shfl_xor_sync(0xffffffffu, tmx1, 2));
    if (tq == 0) {
      redm[wn * 64 + row0] = tmx0;
      redm[wn * 64 + row0 + 8] = tmx1;
    }
    __syncthreads();   // barrier A

    const float fm0 = fmaxf(redm[row0], redm[64 + row0]);
    const float fm1 = fmaxf(redm[row0 + 8], redm[64 + row0 + 8]);
    const float mn0 = fmaxf(m0, fm0), mn1 = fmaxf(m1, fm1);
    const float al0 = __expf(m0 - mn0), al1 = __expf(m1 - mn1);
    m0 = mn0; m1 = mn1;

    float rs0 = 0.f, rs1 = 0.f;
#pragma unroll
    for (int nf = 0; nf < 4; ++nf) {
      float p0 = __expf(sa[nf][0] - mn0);
      float p1 = __expf(sa[nf][1] - mn0);
      float p2 = __expf(sa[nf][2] - mn1);
      float p3 = __expf(sa[nf][3] - mn1);
      rs0 += p0 + p1; rs1 += p2 + p3;
      sa[nf][0] = p0; sa[nf][1] = p1; sa[nf][2] = p2; sa[nf][3] = p3;
    }
    rs0 += __shfl_xor_sync(0xffffffffu, rs0, 1);
    rs0 += __shfl_xor_sync(0xffffffffu, rs0, 2);
    rs1 += __shfl_xor_sync(0xffffffffu, rs1, 1);
    rs1 += __shfl_xor_sync(0xffffffffu, rs1, 2);
    if (tq == 0) {
      reds[wn * 64 + row0] = rs0;
      reds[wn * 64 + row0 + 8] = rs1;
    }

#pragma unroll
    for (int nf = 0; nf < 8; ++nf) {
      oacc[nf][0] *= al0; oacc[nf][1] *= al0;
      oacc[nf][2] *= al1; oacc[nf][3] *= al1;
    }

#pragma unroll
    for (int nf = 0; nf < 4; ++nf) {
      const int pcol = wn * 32 + nf * 8 + 2 * tq;
      __nv_bfloat16 h0 = __float2bfloat16(sa[nf][0]);
      __nv_bfloat16 h1 = __float2bfloat16(sa[nf][1]);
      __nv_bfloat16 h2 = __float2bfloat16(sa[nf][2]);
      __nv_bfloat16 h3 = __float2bfloat16(sa[nf][3]);
      __nv_bfloat162 ph01; ph01.x = h0; ph01.y = h1;
      __nv_bfloat162 ph23; ph23.x = h2; ph23.y = h3;
      __nv_bfloat162 pl01, pl23;
      pl01.x = __float2bfloat16(sa[nf][0] - __bfloat162float(h0));
      pl01.y = __float2bfloat16(sa[nf][1] - __bfloat162float(h1));
      pl23.x = __float2bfloat16(sa[nf][2] - __bfloat162float(h2));
      pl23.y = __float2bfloat16(sa[nf][3] - __bfloat162float(h3));
      *(__nv_bfloat162*)(sb + SM_PH + row0 * LDP + pcol) = ph01;
      *(__nv_bfloat162*)(sb + SM_PH + (row0 + 8) * LDP + pcol) = ph23;
      *(__nv_bfloat162*)(sb + SM_PL + row0 * LDP + pcol) = pl01;
      *(__nv_bfloat162*)(sb + SM_PL + (row0 + 8) * LDP + pcol) = pl23;
    }
    cp_wait0();        // V ready (load overlapped S + softmax)
    __syncthreads();   // barrier B

    l0 = l0 * al0 + (reds[row0] + reds[64 + row0]);
    l1 = l1 * al1 + (reds[row0 + 8] + reds[64 + row0 + 8]);

#pragma unroll
    for (int k0i = 0; k0i < 64; k0i += 16) {
      uint32_t pah[4], pal[4];
      const uint32_t po = (uint32_t)((arow * LDP + k0i + kcol8) * 2);
      ldmx4(pah, sbase + SM_PH * 2 + po);
      ldmx4(pal, sbase + SM_PL * 2 + po);
#pragma unroll
      for (int df = 0; df < 4; ++df) {
        uint32_t th[4], tl[4];
        const uint32_t bo = (uint32_t)(((k0i + vrow) * LDK + wn * 64 + df * 16 + kcol8) * 2);
        ldmx4t(th, sbase + SM_VH * 2 + bo);
        ldmx4t(tl, sbase + SM_VL * 2 + bo);
        mma_bf16(oacc[df * 2],     pah, th[0], th[1]);
        mma_bf16(oacc[df * 2],     pah, tl[0], tl[1]);
        mma_bf16(oacc[df * 2],     pal, th[0], th[1]);
        mma_bf16(oacc[df * 2 + 1], pah, th[2], th[3]);
        mma_bf16(oacc[df * 2 + 1], pah, tl[2], tl[3]);
        mma_bf16(oacc[df * 2 + 1], pal, th[2], th[3]);
      }
    }
  }

  const float inv0 = 1.f / l0, inv1 = 1.f / l1;
  const size_t gr0 = (size_t)(b * Lr + q0 + row0) * HID_C;
  const size_t gr1 = gr0 + (size_t)8 * HID_C;
#pragma unroll
  for (int nf = 0; nf < 8; ++nf) {
    const int col = h * D_C + wn * 64 + nf * 8 + 2 * tq;
    float o0 = oacc[nf][0] * inv0, o1 = oacc[nf][1] * inv0;
    float o2 = oacc[nf][2] * inv1, o3 = oacc[nf][3] * inv1;
    __nv_bfloat162 h01, h23, l01, l23;
    h01.x = __float2bfloat16(o0); h01.y = __float2bfloat16(o1);
    h23.x = __float2bfloat16(o2); h23.y = __float2bfloat16(o3);
    l01.x = __float2bfloat16(o0 - __bfloat162float(h01.x));
    l01.y = __float2bfloat16(o1 - __bfloat162float(h01.y));
    l23.x = __float2bfloat16(o2 - __bfloat162float(h23.x));
    l23.y = __float2bfloat16(o3 - __bfloat162float(h23.y));
    *(__nv_bfloat162*)(Oh + gr0 + col) = h01;
    *(__nv_bfloat162*)(Oh + gr1 + col) = h23;
    *(__nv_bfloat162*)(Ol + gr0 + col) = l01;
    *(__nv_bfloat162*)(Ol + gr1 + col) = l23;
  }
}

// ---------------------------------------------------------------------------
// kernel_launch: x, cos, sin, wq, bq, wk, bk, wv, bv, wo
// ---------------------------------------------------------------------------
extern "C" void kernel_launch(void* const* d_in, const int* in_sizes, int n_in,
                              void* d_out, int out_size) {
  const float* x  = (const float*)d_in[0];
  const float* cs = (const float*)d_in[1];
  const float* sn = (const float*)d_in[2];
  const float* wq = (const float*)d_in[3];
  const float* bq = (const float*)d_in[4];
  const float* wk = (const float*)d_in[5];
  const float* bk = (const float*)d_in[6];
  const float* wv = (const float*)d_in[7];
  const float* bv = (const float*)d_in[8];
  const float* wo = (const float*)d_in[9];
  float* out = (float*)d_out;

  const int Lr = in_sizes[1] / 128;
  const int Mr = in_sizes[0] / HID_C;
  const int NKV = KV_C * D_C;

  void *qkvp, *bcp;
  void *xh, *xl, *wch, *wcl, *woh, *wol, *ah, *al;
  void *qhp, *qlp, *khp, *klp, *vhp, *vlp;
  cudaGetSymbolAddress(&qkvp, g_qkv);  cudaGetSymbolAddress(&bcp, g_bcat);
  cudaGetSymbolAddress(&xh, g_xh);     cudaGetSymbolAddress(&xl, g_xl);
  cudaGetSymbolAddress(&wch, g_wcath); cudaGetSymbolAddress(&wcl, g_wcatl);
  cudaGetSymbolAddress(&woh, g_woh);   cudaGetSymbolAddress(&wol, g_wol);
  cudaGetSymbolAddress(&ah, g_ah);     cudaGetSymbolAddress(&al, g_al);
  cudaGetSymbolAddress(&qhp, g_qh);    cudaGetSymbolAddress(&qlp, g_ql);
  cudaGetSymbolAddress(&khp, g_kh);    cudaGetSymbolAddress(&klp, g_kl);
  cudaGetSymbolAddress(&vhp, g_vh);    cudaGetSymbolAddress(&vlp, g_vl);

  cudaFuncSetAttribute(gemm_bf16x3<true>,  cudaFuncAttributeMaxDynamicSharedMemorySize, GEMM_SMEM);
  cudaFuncSetAttribute(gemm_bf16x3<false>, cudaFuncAttributeMaxDynamicSharedMemorySize, GEMM_SMEM);
  cudaFuncSetAttribute(flash_mma,          cudaFuncAttributeMaxDynamicSharedMemorySize, FLASH2_SMEM);

  dim3 blk(256);

  auto split = [&](const float* src, void* hi, void* lo, int n) {
    int n4 = n / 4;
    split_kernel<<<(n4 + 255) / 256, blk>>>(src, (__nv_bfloat16*)hi, (__nv_bfloat16*)lo, n4);
  };

  __nv_bfloat16* wcath = (__nv_bfloat16*)wch;
  __nv_bfloat16* wcatl = (__nv_bfloat16*)wcl;

  // launches 0-3: splits of x and QKV weights (weights go straight into concat buffer)
  split(x,  xh, xl, Mr * HID_C);
  split(wq, wcath,                          wcatl,                          HID_C * HID_C);
  split(wk, wcath + (size_t)HID_C * HID_C,  wcatl + (size_t)HID_C * HID_C,  NKV * HID_C);
  split(wv, wcath + (size_t)(HID_C + NKV) * HID_C,
            wcatl + (size_t)(HID_C + NKV) * HID_C, NKV * HID_C);
  // launch 4: bias concat
  bias_concat<<<(NCAT + 255) / 256, blk>>>(bq, bk, bv, (float*)bcp);

  // launch 5: fused QKV projection (N=2560) — profiled by ncu -s 5
  dim3 gqkv(NCAT / 128, Mr / 128);
  gemm_bf16x3<true><<<gqkv, blk, GEMM_SMEM>>>(
      (const __nv_bfloat16*)xh, (const __nv_bfloat16*)xl,
      wcath, wcatl, (const float*)bcp, (float*)qkvp, Mr, NCAT, HID_C);

  // split wo (needed only before the final gemm)
  split(wo, woh, wol, HID_C * HID_C);

  // RoPE + split q,k from fused buffer; split v from fused buffer
  const int rt = Mr * (H_C + KV_C) * 64;
  rope_split<<<(rt + 255) / 256, blk>>>((const float*)qkvp, cs, sn,
                                        (__nv_bfloat16*)qhp, (__nv_bfloat16*)qlp,
                                        (__nv_bfloat16*)khp, (__nv_bfloat16*)klp, Lr, Mr);
  {
    int n4 = Mr * 64;
    split_v_strided<<<(n4 + 255) / 256, blk>>>((const float*)qkvp,
                                               (__nv_bfloat16*)vhp, (__nv_bfloat16*)vlp, n4);
  }

  // Flash attention (writes bf16 hi/lo output)
  dim3 gf(Lr / 64, H_C, Mr / Lr);
  flash_mma<<<gf, blk, FLASH2_SMEM>>>(
      (const __nv_bfloat16*)qhp, (const __nv_bfloat16*)qlp,
      (const __nv_bfloat16*)khp, (const __nv_bfloat16*)klp,
      (const __nv_bfloat16*)vhp, (const __nv_bfloat16*)vlp,
      (__nv_bfloat16*)ah, (__nv_bfloat16*)al, Lr);

  // Output projection
  dim3 go(HID_C / 128, Mr / 128);
  gemm_bf16x3<false><<<go, blk, GEMM_SMEM>>>(
      (const __nv_bfloat16*)ah, (const __nv_bfloat16*)al,
      (const __nv_bfloat16*)woh, (const __nv_bfloat16*)wol,
      nullptr, out, Mr, HID_C, HID_C);
}